// round 8
// baseline (speedup 1.0000x reference)
#include <cuda_runtime.h>
#include <cuda_bf16.h>
#include <math.h>
#include <stdint.h>

#define BATCH 256
#define TSEQ  96
#define PRED  96
#define CIN   321
#define DM    512
#define G4    2048
#define HD    (BATCH*DM)
#define NSTEP (TSEQ+PRED-1)     // 191

#define AIMG  36864u            // bf16 image: 256 rows x 144 B per (chunk,split)
#define WIMG  9216u             // bf16 W image: 64 rows x 144 B
#define XIMG  (24576u*144u)
#define A8IMG 16384u            // int8 A image: 256 rows x 64 B per (chunk,split)
#define W8IMG 4096u             // int8 W image: 64 rows x 64 B per (ntile,chunk,split)

// ---------------- device scratch ----------------------------------------------
__device__ float g_mean[BATCH*CIN];
__device__ float g_std [BATCH*CIN];
__device__ float g_istd[BATCH*CIN];
__device__ float g_Gx  [(size_t)BATCH*TSEQ*G4];
__device__ float g_Wd  [G4*DM];
__device__ float g_bd  [G4];
__device__ float g_benc[G4];
__device__ float g_rsc [2][G4];                   // per-row dequant scale (enc,dec)
__device__ unsigned g_flags[NSTEP*32];            // [s][mq4][chunk8], 4 producers each
// int8 hidden images: [par2][chunk8][split2][256][64]
__device__ __align__(1024) unsigned char g_Hbf8[2*8*2*A8IMG];
// decoder hidden bf16 split images for outmma: [d96][chunk8][split2][256][72]
__device__ __align__(1024) unsigned char g_Dbf[(size_t)96*8*2*AIMG];
// int8 recurrent W images: [ntile32][chunk8][split2][64][64]
__device__ __align__(1024) unsigned char g_W8e[32*8*2*W8IMG];
__device__ __align__(1024) unsigned char g_W8d[32*8*2*W8IMG];
// gx operand images (bf16)
__device__ __align__(1024) unsigned char g_Xbf[6*2*XIMG];
__device__ __align__(1024) unsigned char g_WIe[32*6*2*WIMG];
// Wp images for out: [ntile6][chunk8][split2][64][72]
__device__ __align__(1024) unsigned char g_WPe[6*8*2*WIMG];

// ---------------- helpers ------------------------------------------------------
__device__ __forceinline__ float sigf(float x) { return 1.f / (1.f + expf(-x)); }

__device__ __forceinline__ unsigned long long dup2(float x) {
    unsigned long long r;
    asm("mov.b64 %0, {%1, %2};" : "=l"(r) : "f"(x), "f"(x));
    return r;
}
__device__ __forceinline__ void fma2(unsigned long long& d, unsigned long long a, unsigned long long b) {
    asm("fma.rn.f32x2 %0, %1, %2, %0;" : "+l"(d) : "l"(a), "l"(b));
}
__device__ __forceinline__ float lo32(unsigned long long v) { return __uint_as_float((unsigned)v); }
__device__ __forceinline__ float hi32(unsigned long long v) { return __uint_as_float((unsigned)(v >> 32)); }

__device__ __forceinline__ uint32_t smem_u32(const void* p) {
    uint32_t a;
    asm("{ .reg .u64 t; cvta.to.shared.u64 t, %1; cvt.u32.u64 %0, t; }" : "=r"(a) : "l"(p));
    return a;
}
__device__ __forceinline__ void cpasync16(uint32_t dst, const void* src) {
    asm volatile("cp.async.cg.shared.global [%0], [%1], 16;" :: "r"(dst), "l"(src) : "memory");
}
#define CP_COMMIT() asm volatile("cp.async.commit_group;" ::: "memory")
#define CP_WAIT(N)  asm volatile("cp.async.wait_group %0;" :: "n"(N) : "memory")

__device__ __forceinline__ void ldsm4(uint32_t* r, uint32_t addr) {
    asm volatile("ldmatrix.sync.aligned.m8n8.x4.shared.b16 {%0,%1,%2,%3}, [%4];"
        : "=r"(r[0]), "=r"(r[1]), "=r"(r[2]), "=r"(r[3]) : "r"(addr));
}
__device__ __forceinline__ void mma16816(float* d, const uint32_t* a, const uint32_t* b) {
    asm volatile("mma.sync.aligned.m16n8k16.row.col.f32.bf16.bf16.f32 "
        "{%0,%1,%2,%3}, {%4,%5,%6,%7}, {%8,%9}, {%0,%1,%2,%3};"
        : "+f"(d[0]), "+f"(d[1]), "+f"(d[2]), "+f"(d[3])
        : "r"(a[0]), "r"(a[1]), "r"(a[2]), "r"(a[3]), "r"(b[0]), "r"(b[1]));
}
__device__ __forceinline__ void imma16832(int* d, const uint32_t* a, const uint32_t* b) {
    asm volatile("mma.sync.aligned.m16n8k32.row.col.s32.s8.s8.s32 "
        "{%0,%1,%2,%3}, {%4,%5,%6,%7}, {%8,%9}, {%0,%1,%2,%3};"
        : "+r"(d[0]), "+r"(d[1]), "+r"(d[2]), "+r"(d[3])
        : "r"(a[0]), "r"(a[1]), "r"(a[2]), "r"(a[3]), "r"(b[0]), "r"(b[1]));
}
__device__ __forceinline__ void bfsplit2(float a, float b, uint32_t& hw, uint32_t& lw) {
    __nv_bfloat16 h0 = __float2bfloat16(a), h1 = __float2bfloat16(b);
    float r0 = a - __bfloat162float(h0), r1 = b - __bfloat162float(h1);
    __nv_bfloat16 l0 = __float2bfloat16(r0), l1 = __float2bfloat16(r1);
    hw = (uint32_t)__bfloat16_as_ushort(h0) | ((uint32_t)__bfloat16_as_ushort(h1) << 16);
    lw = (uint32_t)__bfloat16_as_ushort(l0) | ((uint32_t)__bfloat16_as_ushort(l1) << 16);
}
__device__ __forceinline__ void spin_flag4(const unsigned* p) {
    unsigned v;
    do {
        asm volatile("ld.acquire.gpu.u32 %0, [%1];" : "=r"(v) : "l"(p) : "memory");
    } while (v < 4u);
}

// ---------------- stats --------------------------------------------------------
__global__ __launch_bounds__(256) void stats_kernel(const float* __restrict__ x) {
    int idx = blockIdx.x * 256 + threadIdx.x;
    if (idx >= BATCH * CIN) return;
    int b = idx / CIN, ch = idx % CIN;
    float s = 0.f, ss = 0.f;
    const float* p = x + (size_t)b * TSEQ * CIN + ch;
    #pragma unroll 4
    for (int t = 0; t < TSEQ; t++) { float v = p[t * CIN]; s += v; ss += v * v; }
    float mean = s * (1.f / TSEQ);
    float var = ss * (1.f / TSEQ) - mean * mean;
    if (var < 0.f) var = 0.f;
    float sd = sqrtf(var + 1e-5f);
    g_mean[idx] = mean; g_std[idx] = sd; g_istd[idx] = 1.f / sd;
}

// ---------------- bias fold ----------------------------------------------------
__global__ __launch_bounds__(256) void bias_kernel(const float* __restrict__ bih,
                                                   const float* __restrict__ bhh,
                                                   const float* __restrict__ Wih,
                                                   const float* __restrict__ bp) {
    int n = blockIdx.x * 256 + threadIdx.x;
    if (n >= G4) return;
    float be = bih[n] + bhh[n];
    float s = 0.f;
    const float* w = Wih + (size_t)n * CIN;
    for (int j = 0; j < CIN; j++) s += w[j] * bp[j];
    g_benc[n] = be;
    g_bd[n] = be + s;
}

// ---------------- Wd = Whh + Wih @ Wp ------------------------------------------
__global__ __launch_bounds__(256) void wd_kernel(const float* __restrict__ Wih,
                                                 const float* __restrict__ Wp,
                                                 const float* __restrict__ Whh) {
    __shared__ float As[64 * 17];
    __shared__ float Bs[16 * 65];
    int tid = threadIdx.x;
    int n0 = blockIdx.x * 64;
    int m0 = blockIdx.y * 64;
    int tr = tid >> 4, tc = tid & 15;
    float acc[4][4] = {};
    for (int j0 = 0; j0 < CIN; j0 += 16) {
        #pragma unroll
        for (int i = 0; i < 4; i++) {
            int l = tid + 256 * i;
            int mr = l >> 4, jj = l & 15;
            int j = j0 + jj;
            As[mr * 17 + jj] = (j < CIN) ? Wih[(size_t)(m0 + mr) * CIN + j] : 0.f;
        }
        #pragma unroll
        for (int i = 0; i < 4; i++) {
            int l = tid + 256 * i;
            int jj = l >> 6, nr = l & 63;
            int j = j0 + jj;
            Bs[jj * 65 + nr] = (j < CIN) ? Wp[(size_t)j * DM + n0 + nr] : 0.f;
        }
        __syncthreads();
        #pragma unroll
        for (int jj = 0; jj < 16; jj++) {
            float a[4], bb[4];
            #pragma unroll
            for (int r = 0; r < 4; r++) a[r] = As[(tr * 4 + r) * 17 + jj];
            #pragma unroll
            for (int cc = 0; cc < 4; cc++) bb[cc] = Bs[jj * 65 + tc * 4 + cc];
            #pragma unroll
            for (int r = 0; r < 4; r++)
                #pragma unroll
                for (int cc = 0; cc < 4; cc++) acc[r][cc] += a[r] * bb[cc];
        }
        __syncthreads();
    }
    #pragma unroll
    for (int r = 0; r < 4; r++) {
        int m = m0 + tr * 4 + r;
        #pragma unroll
        for (int cc = 0; cc < 4; cc++) {
            int n = n0 + tc * 4 + cc;
            g_Wd[(size_t)m * DM + n] = Whh[(size_t)m * DM + n] + acc[r][cc];
        }
    }
}

// ---------------- int8 W image builder (gate-interleaved rows, per-row scale) --
// image row rr = joct*32 + gate*8 + j7  ->  src row gate*512 + ntile*16 + joct*8 + j7
__global__ __launch_bounds__(256) void wq_kernel(const float* __restrict__ src,
                                                 unsigned char* __restrict__ dst,
                                                 int variant) {
    int ntile = blockIdx.x;   // 0..31
    int tid = threadIdx.x;
    int rr = tid >> 2;        // 0..63
    int q  = tid & 3;         // K quarter (128 each)
    int joct = rr >> 5, gate = (rr >> 3) & 3, j7 = rr & 7;
    int srow = gate * DM + ntile * 16 + joct * 8 + j7;
    const float* wrow = src + (size_t)srow * DM;

    float mx = 0.f;
    for (int k = q * 128; k < q * 128 + 128; k++) mx = fmaxf(mx, fabsf(wrow[k]));
    mx = fmaxf(mx, __shfl_xor_sync(0xFFFFFFFFu, mx, 1));
    mx = fmaxf(mx, __shfl_xor_sync(0xFFFFFFFFu, mx, 2));
    float qs = (mx > 1e-30f) ? (32500.f / mx) : 0.f;
    if (q == 0) g_rsc[variant][srow] = (mx > 1e-30f) ? (mx / (16384.f * 32500.f)) : 0.f;

    for (int k = q * 128; k < q * 128 + 128; k++) {
        int wq = __float2int_rn(wrow[k] * qs);
        int w1 = (wq + 128) >> 8;
        int w2 = wq - (w1 << 8);
        int chunk = k >> 6, kc = k & 63;
        unsigned char* d0 = dst + ((size_t)(ntile * 8 + chunk) * 2) * W8IMG;
        d0[rr * 64 + kc]          = (unsigned char)(signed char)w1;
        d0[W8IMG + rr * 64 + kc]  = (unsigned char)(signed char)w2;
    }
}

// ---------------- Wih image builder for gx (bf16) ------------------------------
__global__ __launch_bounds__(256) void wihsplit_kernel(const float* __restrict__ Wih) {
    int chunk = blockIdx.x;
    int ntile = blockIdx.y;
    int tid = threadIdx.x;
    int rr = tid >> 2;
    int q  = tid & 3;
    int srow = ntile * 64 + rr;
    unsigned char* d0 = g_WIe + ((size_t)(ntile * 6 + chunk) * 2) * WIMG;
    #pragma unroll
    for (int c = 0; c < 18; c++) {
        int col = q * 18 + c;
        int k = chunk * 64 + col;
        float v = (col < 64 && k < CIN) ? Wih[(size_t)srow * CIN + k] : 0.f;
        __nv_bfloat16 hb = __float2bfloat16(v);
        float rem2 = v - __bfloat162float(hb);
        __nv_bfloat16 lb = __float2bfloat16(rem2);
        size_t off = (size_t)rr * 144 + col * 2;
        *(__nv_bfloat16*)(d0 + off)        = hb;
        *(__nv_bfloat16*)(d0 + WIMG + off) = lb;
    }
}

// ---------------- Wp image builder for out (bf16) ------------------------------
__global__ __launch_bounds__(256) void wpsplit_kernel(const float* __restrict__ Wp) {
    int chunk = blockIdx.x;
    int ntile = blockIdx.y;
    int tid = threadIdx.x;
    int rr = tid >> 2;
    int q  = tid & 3;
    int n = ntile * 64 + rr;
    unsigned char* d0 = g_WPe + ((size_t)(ntile * 8 + chunk) * 2) * WIMG;
    #pragma unroll
    for (int c = 0; c < 18; c++) {
        int col = q * 18 + c;
        int k = chunk * 64 + col;
        float v = (col < 64 && n < CIN) ? Wp[(size_t)n * DM + k] : 0.f;
        __nv_bfloat16 hb = __float2bfloat16(v);
        float rem2 = v - __bfloat162float(hb);
        __nv_bfloat16 lb = __float2bfloat16(rem2);
        size_t off = (size_t)rr * 144 + col * 2;
        *(__nv_bfloat16*)(d0 + off)        = hb;
        *(__nv_bfloat16*)(d0 + WIMG + off) = lb;
    }
}

// ---------------- x normalize+split images (bf16) ------------------------------
__global__ __launch_bounds__(256) void xsplit_kernel(const float* __restrict__ x) {
    int idx = blockIdx.x * 256 + threadIdx.x;
    if (idx >= BATCH * TSEQ * CIN) return;
    int m = idx / CIN, k = idx - m * CIN;
    int b = m / TSEQ;
    int bc = b * CIN + k;
    float v = (x[idx] - g_mean[bc]) * g_istd[bc];
    __nv_bfloat16 hb = __float2bfloat16(v);
    float rem = v - __bfloat162float(hb);
    __nv_bfloat16 lb = __float2bfloat16(rem);
    int chunk = k >> 6, col = k & 63;
    size_t offh = ((size_t)(chunk * 2) * 24576 + m) * 144 + col * 2;
    *(__nv_bfloat16*)(g_Xbf + offh)        = hb;
    *(__nv_bfloat16*)(g_Xbf + offh + XIMG) = lb;
}

// ---------------- init ----------------------------------------------------------
__global__ __launch_bounds__(256) void init_kernel() {
    int i = blockIdx.x * 256 + threadIdx.x;
    if (i < (int)(sizeof(g_Hbf8) / 4)) ((uint32_t*)g_Hbf8)[i] = 0u;
    if (i < NSTEP * 32) g_flags[i] = 0u;
}

// ---------------- gx = xnorm @ Wih^T via HMMA split ----------------------------
#define GXSTAGE 55296
#define GX_SMEM (2*GXSTAGE)
__global__ void __launch_bounds__(256, 1) gxmma_kernel() {
    extern __shared__ unsigned char smem[];
    const int tid = threadIdx.x;
    const int w = tid >> 5, lane = tid & 31;
    const int n0 = blockIdx.x * 64;
    const int m0 = blockIdx.y * 128;
    uint32_t sbase = smem_u32(smem);
    float acc[8][4];
    #pragma unroll
    for (int f = 0; f < 8; f++)
        #pragma unroll
        for (int r = 0; r < 4; r++) acc[f][r] = 0.f;

    const uint32_t aoff = (uint32_t)((w * 16 + (lane & 15)) * 144 + (lane >> 4) * 16);
    const uint32_t boff = (uint32_t)(((((lane >> 4) & 1) * 8) + (lane & 7)) * 144 + ((lane >> 3) & 1) * 16);
    const unsigned char* Bbase = g_WIe + ((size_t)blockIdx.x * 6 * 2) * WIMG;

    auto issue = [&](int chunk, int buf) {
        uint32_t sb = sbase + buf * GXSTAGE;
        #pragma unroll
        for (int i = 0; i < 14; i++) {
            int idx = tid + i * 256;
            if (idx >= 3456) break;
            uint32_t dst; const unsigned char* src;
            if (idx < 2304) {
                int sp = idx / 1152; int off = (idx - sp * 1152) * 16;
                dst = sb + sp * 18432 + off;
                src = g_Xbf + (size_t)(chunk * 2 + sp) * XIMG + (size_t)m0 * 144 + off;
            } else {
                int j = idx - 2304; int sp = j / 576; int off = (j - sp * 576) * 16;
                dst = sb + 36864 + sp * 9216 + off;
                src = Bbase + (size_t)(chunk * 2 + sp) * WIMG + off;
            }
            cpasync16(dst, src);
        }
        CP_COMMIT();
    };

    issue(0, 0); issue(1, 1);
    #pragma unroll 1
    for (int c = 0; c < 6; c++) {
        if (c < 5) { CP_WAIT(1); } else { CP_WAIT(0); }
        __syncthreads();
        uint32_t st = sbase + (c & 1) * GXSTAGE;
        uint32_t sAhi = st, sAlo = st + 18432, sWhi = st + 36864, sWlo = st + 46080;
        #pragma unroll
        for (int kf = 0; kf < 4; kf++) {
            uint32_t ah[4], al[4], bh[4][4], bl[4][4];
            ldsm4(ah, sAhi + aoff + kf * 32);
            ldsm4(al, sAlo + aoff + kf * 32);
            #pragma unroll
            for (int ng = 0; ng < 4; ng++) {
                ldsm4(bh[ng], sWhi + boff + ng * 2304 + kf * 32);
                ldsm4(bl[ng], sWlo + boff + ng * 2304 + kf * 32);
            }
            #pragma unroll
            for (int ng = 0; ng < 4; ng++) { mma16816(acc[2*ng], ah, bh[ng]); mma16816(acc[2*ng+1], ah, bh[ng]+2); }
            #pragma unroll
            for (int ng = 0; ng < 4; ng++) { mma16816(acc[2*ng], ah, bl[ng]); mma16816(acc[2*ng+1], ah, bl[ng]+2); }
            #pragma unroll
            for (int ng = 0; ng < 4; ng++) { mma16816(acc[2*ng], al, bh[ng]); mma16816(acc[2*ng+1], al, bh[ng]+2); }
        }
        __syncthreads();
        if (c + 2 < 6) issue(c + 2, c & 1);
    }
    #pragma unroll
    for (int f = 0; f < 8; f++) {
        int n = n0 + (f >> 1) * 16 + (f & 1) * 8 + (lane & 3) * 2;
        #pragma unroll
        for (int rowi = 0; rowi < 2; rowi++) {
            int m = m0 + w * 16 + (lane >> 2) + rowi * 8;
            *(float2*)&g_Gx[(size_t)m * G4 + n] = make_float2(acc[f][rowi*2], acc[f][rowi*2+1]);
        }
    }
}

// ---------------- persistent LSTM kernel (INT8 IMMA) ---------------------------
// grid (32 ntile, 4 mq), 256 thr. smem pitch 80B for ldsm; W cache resident.
#define WCH_B    10240                 // per chunk: 2 splits x 64 rows x 80 B
#define WCACHE_B (8*WCH_B)             // 81920
#define ABUF_B   10240
#define PERSIST_SMEM (WCACHE_B + 3*ABUF_B)   // 112640

__global__ void __launch_bounds__(256, 1) persist_kernel(const float* __restrict__ gx,
                                                         const float* __restrict__ benc,
                                                         const float* __restrict__ bd) {
    extern __shared__ unsigned char smem[];
    const int tid = threadIdx.x;
    const int w = tid >> 5, lane = tid & 31;
    const int wr = w & 3, wc = w >> 2;
    const int ntile = blockIdx.x, mq = blockIdx.y;
    uint32_t sbase = smem_u32(smem);
    uint32_t Wc = sbase;
    uint32_t Ab = sbase + WCACHE_B;

    // ldsm addressing (pitch 80)
    const uint32_t aoff = (uint32_t)((wr * 16 + (lane & 15)) * 80 + (lane >> 4) * 16);
    const uint32_t boff = (uint32_t)((wc * 32 + ((lane >> 4) & 1) * 8 + (lane & 7)) * 80 + ((lane >> 3) & 1) * 16);

    const unsigned char* WEsrc = g_W8e + (size_t)(ntile * 8) * 2 * W8IMG;
    const unsigned char* WDsrc = g_W8d + (size_t)(ntile * 8) * 2 * W8IMG;

    auto loadW = [&](const unsigned char* src) {
        #pragma unroll 4
        for (int i = 0; i < 16; i++) {
            int idx = tid + i * 256;                 // 0..4095
            int chunk = idx >> 9;
            int rem = idx & 511;
            int split = rem >> 8;
            int row = (rem >> 2) & 63;
            int sub = rem & 3;
            cpasync16(Wc + chunk * WCH_B + split * 5120 + row * 80 + sub * 16,
                      src + (size_t)idx * 16);
        }
        CP_COMMIT();
    };
    auto loadA = [&](const unsigned char* Apar, int chunk, int buf) {
        #pragma unroll
        for (int i = 0; i < 2; i++) {
            int idx = tid + i * 256;                 // 0..511
            int split = idx >> 8;
            int row = (idx >> 2) & 63;
            int sub = idx & 3;
            cpasync16(Ab + buf * ABUF_B + split * 5120 + row * 80 + sub * 16,
                      Apar + (size_t)(chunk * 2 + split) * A8IMG + mq * 4096 + (size_t)(idx & 255) * 16);
        }
        CP_COMMIT();
    };

    const int j0 = ntile * 16 + wc * 8 + (lane & 3) * 2;
    const int bbase = mq * 64 + wr * 16 + (lane >> 2);
    const int chunkA = ntile >> 2;
    const int col8 = (ntile & 3) * 16 + wc * 8 + (lane & 3) * 2;       // int8 image col
    const size_t colOff = (size_t)col8 * 2;                            // bf16 dec image col

    float bi[4][2], rs[4][2];
    #pragma unroll
    for (int g = 0; g < 4; g++) {
        bi[g][0] = benc[g * DM + j0]; bi[g][1] = benc[g * DM + j0 + 1];
        rs[g][0] = g_rsc[0][g * DM + j0]; rs[g][1] = g_rsc[0][g * DM + j0 + 1];
    }
    float creg[4] = {0.f, 0.f, 0.f, 0.f};

    loadW(WEsrc);
    CP_WAIT(0);
    __syncthreads();

    for (int s = 0; s < NSTEP; s++) {
        const bool enc = (s < TSEQ);
        if (s == TSEQ) {
            __syncthreads();
            loadW(WDsrc);
            #pragma unroll
            for (int g = 0; g < 4; g++) {
                bi[g][0] = bd[g * DM + j0]; bi[g][1] = bd[g * DM + j0 + 1];
                rs[g][0] = g_rsc[1][g * DM + j0]; rs[g][1] = g_rsc[1][g * DM + j0 + 1];
            }
            CP_WAIT(0);
            __syncthreads();
        }
        const int par = s & 1;
        const unsigned char* Apar = g_Hbf8 + (size_t)(par * 16) * A8IMG;
        const unsigned* fprev = (s > 0) ? &g_flags[(s - 1) * 32 + mq * 8] : nullptr;

        float pr[16];
        if (enc) {
            #pragma unroll
            for (int rowi = 0; rowi < 2; rowi++) {
                const float* gr = gx + ((size_t)(bbase + rowi * 8) * TSEQ + s) * G4;
                #pragma unroll
                for (int g = 0; g < 4; g++) {
                    float2 v = *(const float2*)&gr[g * DM + j0];
                    pr[rowi * 8 + g * 2]     = v.x;
                    pr[rowi * 8 + g * 2 + 1] = v.y;
                }
            }
        }

        int accH[4][4], accL[4][4];
        #pragma unroll
        for (int g = 0; g < 4; g++)
            #pragma unroll
            for (int r = 0; r < 4; r++) { accH[g][r] = 0; accL[g][r] = 0; }

        if (fprev) { spin_flag4(fprev + 0); }
        loadA(Apar, 0, 0);
        if (fprev) { spin_flag4(fprev + 1); }
        loadA(Apar, 1, 1);
        #pragma unroll 1
        for (int c = 0; c < 8; c++) {
            if (c + 2 < 8) {
                if (fprev) { spin_flag4(fprev + c + 2); }
                loadA(Apar, c + 2, (c + 2) % 3);
                CP_WAIT(2);
            }
            else if (c == 6) { CP_WAIT(1); }
            else             { CP_WAIT(0); }
            __syncthreads();
            uint32_t at = Ab + (c % 3) * ABUF_B;
            uint32_t wt = Wc + c * WCH_B;
            #pragma unroll
            for (int kf = 0; kf < 2; kf++) {
                uint32_t a1[4], a2[4], w1a[4], w1b[4], w2a[4], w2b[4];
                ldsm4(a1,  at + aoff + kf * 32);
                ldsm4(a2,  at + 5120 + aoff + kf * 32);
                ldsm4(w1a, wt + boff + kf * 32);
                ldsm4(w1b, wt + boff + 1280 + kf * 32);
                ldsm4(w2a, wt + 5120 + boff + kf * 32);
                ldsm4(w2b, wt + 5120 + boff + 1280 + kf * 32);
                imma16832(accH[0], a1, w1a);     imma16832(accH[1], a1, w1a + 2);
                imma16832(accH[2], a1, w1b);     imma16832(accH[3], a1, w1b + 2);
                imma16832(accL[0], a1, w2a);     imma16832(accL[1], a1, w2a + 2);
                imma16832(accL[2], a1, w2b);     imma16832(accL[3], a1, w2b + 2);
                imma16832(accL[0], a2, w1a);     imma16832(accL[1], a2, w1a + 2);
                imma16832(accL[2], a2, w1b);     imma16832(accL[3], a2, w1b + 2);
            }
            __syncthreads();
        }

        // ---- epilogue ----
        unsigned char* img1 = g_Hbf8 + (size_t)(((par ^ 1) * 8 + chunkA) * 2) * A8IMG;
        unsigned char* img2 = img1 + A8IMG;
        unsigned char* decHi = nullptr;
        if (s >= TSEQ - 1) {
            int d = s - (TSEQ - 1);
            decHi = g_Dbf + (size_t)((d * 8 + chunkA) * 2) * AIMG;
        }

        #pragma unroll
        for (int rowi = 0; rowi < 2; rowi++) {
            int b = bbase + rowi * 8;
            float h2[2];
            #pragma unroll
            for (int cp = 0; cp < 2; cp++) {
                int r = rowi * 2 + cp;
                float gi = fmaf((float)accH[0][r], 65536.f * rs[0][cp], (float)accL[0][r] * 256.f * rs[0][cp]) + bi[0][cp];
                float gf = fmaf((float)accH[1][r], 65536.f * rs[1][cp], (float)accL[1][r] * 256.f * rs[1][cp]) + bi[1][cp];
                float gg = fmaf((float)accH[2][r], 65536.f * rs[2][cp], (float)accL[2][r] * 256.f * rs[2][cp]) + bi[2][cp];
                float go = fmaf((float)accH[3][r], 65536.f * rs[3][cp], (float)accL[3][r] * 256.f * rs[3][cp]) + bi[3][cp];
                if (enc) {
                    gi += pr[rowi * 8 + 0 + cp];
                    gf += pr[rowi * 8 + 2 + cp];
                    gg += pr[rowi * 8 + 4 + cp];
                    go += pr[rowi * 8 + 6 + cp];
                }
                float cn = sigf(gf) * creg[r] + sigf(gi) * tanhf(gg);
                float hn = sigf(go) * tanhf(cn);
                creg[r] = cn;
                h2[cp] = hn;
            }
            // int8 quantize for next step A image
            int h14a = __float2int_rn(h2[0] * 16384.f);
            int h14b = __float2int_rn(h2[1] * 16384.f);
            int h1a = (h14a + 128) >> 8, h2a = h14a - (h1a << 8);
            int h1b = (h14b + 128) >> 8, h2b = h14b - (h1b << 8);
            uint16_t p1 = (uint16_t)((uint8_t)(signed char)h1a | ((uint8_t)(signed char)h1b << 8));
            uint16_t p2 = (uint16_t)((uint8_t)(signed char)h2a | ((uint8_t)(signed char)h2b << 8));
            *(uint16_t*)(img1 + (size_t)b * 64 + col8) = p1;
            *(uint16_t*)(img2 + (size_t)b * 64 + col8) = p2;
            if (decHi) {
                uint32_t hw, lw;
                bfsplit2(h2[0], h2[1], hw, lw);
                size_t off = (size_t)b * 144 + colOff;
                *(uint32_t*)(decHi + off) = hw;
                *(uint32_t*)(decHi + AIMG + off) = lw;
            }
        }

        if (s < NSTEP - 1) {
            __threadfence();
            __syncthreads();
            if (tid == 0) atomicAdd(&g_flags[s * 32 + mq * 8 + chunkA], 1u);
        }
    }
}

// ---------------- out: Y = Dbf @ Wp^T via HMMA, denormalize, scatter -----------
#define OSTAGE 55296
#define OUT_SMEM (2*OSTAGE)
__global__ void __launch_bounds__(256, 1) outmma_kernel(const float* __restrict__ bp,
                                                        float* __restrict__ out) {
    extern __shared__ unsigned char smem[];
    const int tid = threadIdx.x;
    const int w = tid >> 5, lane = tid & 31;
    const int ntile = blockIdx.x;        // 0..5
    const int mt = blockIdx.y;           // 0..191
    const int d = mt >> 1, half = mt & 1;
    const int m0 = half * 128;
    uint32_t sbase = smem_u32(smem);
    float acc[8][4];
    #pragma unroll
    for (int f = 0; f < 8; f++)
        #pragma unroll
        for (int r = 0; r < 4; r++) acc[f][r] = 0.f;

    const uint32_t aoff = (uint32_t)((w * 16 + (lane & 15)) * 144 + (lane >> 4) * 16);
    const uint32_t boff = (uint32_t)(((((lane >> 4) & 1) * 8) + (lane & 7)) * 144 + ((lane >> 3) & 1) * 16);
    const unsigned char* Abase = g_Dbf + (size_t)(d * 16) * AIMG;
    const unsigned char* Bbase = g_WPe + ((size_t)(ntile * 8) * 2) * WIMG;

    auto issue = [&](int chunk, int buf) {
        uint32_t sb = sbase + buf * OSTAGE;
        #pragma unroll
        for (int i = 0; i < 14; i++) {
            int idx = tid + i * 256;
            if (idx >= 3456) break;
            uint32_t dst; const unsigned char* src;
            if (idx < 2304) {
                int sp = idx / 1152; int off = (idx - sp * 1152) * 16;
                dst = sb + sp * 18432 + off;
                src = Abase + (size_t)(chunk * 2 + sp) * AIMG + (size_t)m0 * 144 + off;
            } else {
                int j = idx - 2304; int sp = j / 576; int off = (j - sp * 576) * 16;
                dst = sb + 36864 + sp * 9216 + off;
                src = Bbase + (size_t)(chunk * 2 + sp) * WIMG + off;
            }
            cpasync16(dst, src);
        }
        CP_COMMIT();
    };

    issue(0, 0); issue(1, 1);
    #pragma unroll 1
    for (int c = 0; c < 8; c++) {
        if (c < 7) { CP_WAIT(1); } else { CP_WAIT(0); }
        __syncthreads();
        uint32_t st = sbase + (c & 1) * OSTAGE;
        uint32_t sAhi = st, sAlo = st + 18432, sWhi = st + 36864, sWlo = st + 46080;
        #pragma unroll
        for (int kf = 0; kf < 4; kf++) {
            uint32_t ah[4], al[4], bh[4][4], bl[4][4];
            ldsm4(ah, sAhi + aoff + kf * 32);
            ldsm4(al, sAlo + aoff + kf * 32);
            #pragma unroll
            for (int ng = 0; ng < 4; ng++) {
                ldsm4(bh[ng], sWhi + boff + ng * 2304 + kf * 32);
                ldsm4(bl[ng], sWlo + boff + ng * 2304 + kf * 32);
            }
            #pragma unroll
            for (int ng = 0; ng < 4; ng++) { mma16816(acc[2*ng], ah, bh[ng]); mma16816(acc[2*ng+1], ah, bh[ng]+2); }
            #pragma unroll
            for (int ng = 0; ng < 4; ng++) { mma16816(acc[2*ng], ah, bl[ng]); mma16816(acc[2*ng+1], ah, bl[ng]+2); }
            #pragma unroll
            for (int ng = 0; ng < 4; ng++) { mma16816(acc[2*ng], al, bh[ng]); mma16816(acc[2*ng+1], al, bh[ng]+2); }
        }
        __syncthreads();
        if (c + 2 < 8) issue(c + 2, c & 1);
    }
    #pragma unroll
    for (int f = 0; f < 8; f++) {
        int gn = ntile * 64 + (f >> 1) * 16 + (f & 1) * 8 + (lane & 3) * 2;
        #pragma unroll
        for (int rowi = 0; rowi < 2; rowi++) {
            int b = m0 + w * 16 + (lane >> 2) + rowi * 8;
            #pragma unroll
            for (int cp = 0; cp < 2; cp++) {
                int n = gn + cp;
                if (n < CIN) {
                    int bc = b * CIN + n;
                    float y = acc[f][rowi * 2 + cp] + bp[n];
                    out[(size_t)b * PRED * CIN + (size_t)d * CIN + n] =
                        y * g_std[bc] + g_mean[bc];
                }
            }
        }
    }
}

// ---------------- host launcher ------------------------------------------------
extern "C" void kernel_launch(void* const* d_in, const int* in_sizes, int n_in,
                              void* d_out, int out_size) {
    const float* x   = (const float*)d_in[0];
    const float* Wih = (const float*)d_in[1];
    const float* Whh = (const float*)d_in[2];
    const float* bih = (const float*)d_in[3];
    const float* bhh = (const float*)d_in[4];
    const float* Wp  = (const float*)d_in[5];
    const float* bp  = (const float*)d_in[6];
    float* out = (float*)d_out;

    float *gx, *wd, *bd, *benc;
    unsigned char *w8e, *w8d;
    cudaGetSymbolAddress((void**)&gx,   g_Gx);
    cudaGetSymbolAddress((void**)&wd,   g_Wd);
    cudaGetSymbolAddress((void**)&bd,   g_bd);
    cudaGetSymbolAddress((void**)&benc, g_benc);
    cudaGetSymbolAddress((void**)&w8e,  g_W8e);
    cudaGetSymbolAddress((void**)&w8d,  g_W8d);

    cudaFuncSetAttribute(persist_kernel, cudaFuncAttributeMaxDynamicSharedMemorySize, PERSIST_SMEM);
    cudaFuncSetAttribute(gxmma_kernel, cudaFuncAttributeMaxDynamicSharedMemorySize, GX_SMEM);
    cudaFuncSetAttribute(outmma_kernel, cudaFuncAttributeMaxDynamicSharedMemorySize, OUT_SMEM);

    stats_kernel<<<(BATCH * CIN + 255) / 256, 256>>>(x);
    bias_kernel<<<(G4 + 255) / 256, 256>>>(bih, bhh, Wih, bp);
    wd_kernel<<<dim3(DM / 64, G4 / 64), 256>>>(Wih, Wp, Whh);
    xsplit_kernel<<<(BATCH * TSEQ * CIN + 255) / 256, 256>>>(x);
    wihsplit_kernel<<<dim3(6, 32), 256>>>(Wih);
    wpsplit_kernel<<<dim3(8, 6), 256>>>(Wp);
    wq_kernel<<<32, 256>>>(Whh, w8e, 0);
    wq_kernel<<<32, 256>>>(wd, w8d, 1);
    init_kernel<<<((int)(sizeof(g_Hbf8) / 4) + 255) / 256, 256>>>();
    gxmma_kernel<<<dim3(32, 192), 256, GX_SMEM>>>();

    persist_kernel<<<dim3(32, 4), 256, PERSIST_SMEM>>>(gx, benc, bd);

    outmma_kernel<<<dim3(6, 192), 256, OUT_SMEM>>>(bp, out);
    (void)in_sizes; (void)n_in; (void)out_size;
}

// round 9
// speedup vs baseline: 1.3299x; 1.3299x over previous
#include <cuda_runtime.h>
#include <cuda_bf16.h>
#include <math.h>
#include <stdint.h>

#define BATCH 256
#define TSEQ  96
#define PRED  96
#define CIN   321
#define DM    512
#define G4    2048
#define HD    (BATCH*DM)
#define NSTEP (TSEQ+PRED-1)     // 191

#define AIMG  36864u            // bf16 image: 256 rows x 144 B per (chunk,split)
#define WIMG  9216u             // bf16 W image: 64 rows x 144 B
#define XIMG  (24576u*144u)

// ---------------- device scratch ----------------------------------------------
__device__ float g_mean[BATCH*CIN];
__device__ float g_std [BATCH*CIN];
__device__ float g_istd[BATCH*CIN];
__device__ float g_Gx  [(size_t)BATCH*TSEQ*G4];
__device__ float g_Wd  [G4*DM];
__device__ float g_bd  [G4];
__device__ float g_benc[G4];
__device__ unsigned g_bar[NSTEP*4];               // per (step, mq) counter -> 32
// bf16 hidden images: [par2][chunk8][split2][256][72]
__device__ __align__(1024) unsigned char g_Hbf[2*8*2*AIMG];
// decoder hidden bf16 split images: [d96][chunk8][split2][256][72]
__device__ __align__(1024) unsigned char g_Dbf[(size_t)96*8*2*AIMG];
// recurrent W images: [ntile32][chunk8][split2][64][72]
__device__ __align__(1024) unsigned char g_WTe[32*8*2*WIMG];
__device__ __align__(1024) unsigned char g_WTd[32*8*2*WIMG];
// gx operand images
__device__ __align__(1024) unsigned char g_Xbf[6*2*XIMG];
__device__ __align__(1024) unsigned char g_WIe[32*6*2*WIMG];
// Wp images for out: [ntile6][chunk8][split2][64][72]
__device__ __align__(1024) unsigned char g_WPe[6*8*2*WIMG];

// ---------------- helpers ------------------------------------------------------
__device__ __forceinline__ float sigf(float x) { return 1.f / (1.f + expf(-x)); }

__device__ __forceinline__ uint32_t smem_u32(const void* p) {
    uint32_t a;
    asm("{ .reg .u64 t; cvta.to.shared.u64 t, %1; cvt.u32.u64 %0, t; }" : "=r"(a) : "l"(p));
    return a;
}
__device__ __forceinline__ void cpasync16(uint32_t dst, const void* src) {
    asm volatile("cp.async.cg.shared.global [%0], [%1], 16;" :: "r"(dst), "l"(src) : "memory");
}
#define CP_COMMIT() asm volatile("cp.async.commit_group;" ::: "memory")
#define CP_WAIT(N)  asm volatile("cp.async.wait_group %0;" :: "n"(N) : "memory")

__device__ __forceinline__ void ldsm4(uint32_t* r, uint32_t addr) {
    asm volatile("ldmatrix.sync.aligned.m8n8.x4.shared.b16 {%0,%1,%2,%3}, [%4];"
        : "=r"(r[0]), "=r"(r[1]), "=r"(r[2]), "=r"(r[3]) : "r"(addr));
}
__device__ __forceinline__ void mma16816(float* d, const uint32_t* a, const uint32_t* b) {
    asm volatile("mma.sync.aligned.m16n8k16.row.col.f32.bf16.bf16.f32 "
        "{%0,%1,%2,%3}, {%4,%5,%6,%7}, {%8,%9}, {%0,%1,%2,%3};"
        : "+f"(d[0]), "+f"(d[1]), "+f"(d[2]), "+f"(d[3])
        : "r"(a[0]), "r"(a[1]), "r"(a[2]), "r"(a[3]), "r"(b[0]), "r"(b[1]));
}
__device__ __forceinline__ void bfsplit2(float a, float b, uint32_t& hw, uint32_t& lw) {
    __nv_bfloat16 h0 = __float2bfloat16(a), h1 = __float2bfloat16(b);
    float r0 = a - __bfloat162float(h0), r1 = b - __bfloat162float(h1);
    __nv_bfloat16 l0 = __float2bfloat16(r0), l1 = __float2bfloat16(r1);
    hw = (uint32_t)__bfloat16_as_ushort(h0) | ((uint32_t)__bfloat16_as_ushort(h1) << 16);
    lw = (uint32_t)__bfloat16_as_ushort(l0) | ((uint32_t)__bfloat16_as_ushort(l1) << 16);
}

// ---------------- prep0: stats + bias fold --------------------------------------
__global__ __launch_bounds__(256) void prep0_kernel(const float* __restrict__ x,
                                                    const float* __restrict__ bih,
                                                    const float* __restrict__ bhh,
                                                    const float* __restrict__ Wih,
                                                    const float* __restrict__ bp) {
    int bb = blockIdx.x;
    if (bb < 321) {
        int idx = bb * 256 + threadIdx.x;
        if (idx >= BATCH * CIN) return;
        int b = idx / CIN, ch = idx % CIN;
        float s = 0.f, ss = 0.f;
        const float* p = x + (size_t)b * TSEQ * CIN + ch;
        #pragma unroll 4
        for (int t = 0; t < TSEQ; t++) { float v = p[t * CIN]; s += v; ss += v * v; }
        float mean = s * (1.f / TSEQ);
        float var = ss * (1.f / TSEQ) - mean * mean;
        if (var < 0.f) var = 0.f;
        float sd = sqrtf(var + 1e-5f);
        g_mean[idx] = mean; g_std[idx] = sd; g_istd[idx] = 1.f / sd;
    } else {
        int n = (bb - 321) * 256 + threadIdx.x;
        if (n >= G4) return;
        float be = bih[n] + bhh[n];
        float s = 0.f;
        const float* w = Wih + (size_t)n * CIN;
        for (int j = 0; j < CIN; j++) s += w[j] * bp[j];
        g_benc[n] = be;
        g_bd[n] = be + s;
    }
}

// ---------------- Wd = Whh + Wih @ Wp ------------------------------------------
__global__ __launch_bounds__(256) void wd_kernel(const float* __restrict__ Wih,
                                                 const float* __restrict__ Wp,
                                                 const float* __restrict__ Whh) {
    __shared__ float As[64 * 17];
    __shared__ float Bs[16 * 65];
    int tid = threadIdx.x;
    int n0 = blockIdx.x * 64;
    int m0 = blockIdx.y * 64;
    int tr = tid >> 4, tc = tid & 15;
    float acc[4][4] = {};
    for (int j0 = 0; j0 < CIN; j0 += 16) {
        #pragma unroll
        for (int i = 0; i < 4; i++) {
            int l = tid + 256 * i;
            int mr = l >> 4, jj = l & 15;
            int j = j0 + jj;
            As[mr * 17 + jj] = (j < CIN) ? Wih[(size_t)(m0 + mr) * CIN + j] : 0.f;
        }
        #pragma unroll
        for (int i = 0; i < 4; i++) {
            int l = tid + 256 * i;
            int jj = l >> 6, nr = l & 63;
            int j = j0 + jj;
            Bs[jj * 65 + nr] = (j < CIN) ? Wp[(size_t)j * DM + n0 + nr] : 0.f;
        }
        __syncthreads();
        #pragma unroll
        for (int jj = 0; jj < 16; jj++) {
            float a[4], bb[4];
            #pragma unroll
            for (int r = 0; r < 4; r++) a[r] = As[(tr * 4 + r) * 17 + jj];
            #pragma unroll
            for (int cc = 0; cc < 4; cc++) bb[cc] = Bs[jj * 65 + tc * 4 + cc];
            #pragma unroll
            for (int r = 0; r < 4; r++)
                #pragma unroll
                for (int cc = 0; cc < 4; cc++) acc[r][cc] += a[r] * bb[cc];
        }
        __syncthreads();
    }
    #pragma unroll
    for (int r = 0; r < 4; r++) {
        int m = m0 + tr * 4 + r;
        #pragma unroll
        for (int cc = 0; cc < 4; cc++) {
            int n = n0 + tc * 4 + cc;
            g_Wd[(size_t)m * DM + n] = Whh[(size_t)m * DM + n] + acc[r][cc];
        }
    }
}

// ---------------- device split-helpers -----------------------------------------
__device__ __forceinline__ void store_split(unsigned char* d0, size_t img, size_t off, float v) {
    __nv_bfloat16 hb = __float2bfloat16(v);
    float rem = v - __bfloat162float(hb);
    __nv_bfloat16 lb = __float2bfloat16(rem);
    *(__nv_bfloat16*)(d0 + off)       = hb;
    *(__nv_bfloat16*)(d0 + img + off) = lb;
}

// ---------------- megasplit: x, Wih, Wp, WTe, WTd image builders ---------------
#define XBLKS 30816
__global__ __launch_bounds__(256) void megasplit_kernel(const float* __restrict__ x,
                                                        const float* __restrict__ Wih,
                                                        const float* __restrict__ Wp,
                                                        const float* __restrict__ Whh) {
    int bb = blockIdx.x;
    int tid = threadIdx.x;
    if (bb < XBLKS) {
        int idx = bb * 256 + tid;
        if (idx >= BATCH * TSEQ * CIN) return;
        int m = idx / CIN, k = idx - m * CIN;
        int b = m / TSEQ;
        int bc = b * CIN + k;
        float v = (x[idx] - g_mean[bc]) * g_istd[bc];
        int chunk = k >> 6, col = k & 63;
        size_t offh = ((size_t)(chunk * 2) * 24576 + m) * 144 + col * 2;
        store_split(g_Xbf, XIMG, offh, v);
        return;
    }
    bb -= XBLKS;
    if (bb < 192) {            // wihsplit: chunk 0..5, ntile 0..31
        int chunk = bb % 6, ntile = bb / 6;
        int rr = tid >> 2, q = tid & 3;
        int srow = ntile * 64 + rr;
        unsigned char* d0 = g_WIe + ((size_t)(ntile * 6 + chunk) * 2) * WIMG;
        #pragma unroll
        for (int c = 0; c < 18; c++) {
            int col = q * 18 + c;
            int k = chunk * 64 + col;
            float v = (col < 64 && k < CIN) ? Wih[(size_t)srow * CIN + k] : 0.f;
            if (col < 64) store_split(d0, WIMG, (size_t)rr * 144 + col * 2, v);
        }
        return;
    }
    bb -= 192;
    if (bb < 48) {             // wpsplit: chunk 0..7, ntile 0..5
        int chunk = bb % 8, ntile = bb / 8;
        int rr = tid >> 2, q = tid & 3;
        int n = ntile * 64 + rr;
        unsigned char* d0 = g_WPe + ((size_t)(ntile * 8 + chunk) * 2) * WIMG;
        #pragma unroll
        for (int c = 0; c < 18; c++) {
            int col = q * 18 + c;
            int k = chunk * 64 + col;
            float v = (col < 64 && n < CIN) ? Wp[(size_t)n * DM + k] : 0.f;
            if (col < 64) store_split(d0, WIMG, (size_t)rr * 144 + col * 2, v);
        }
        return;
    }
    bb -= 48;
    {                          // wsplit enc (bb<256) / dec (bb>=256)
        const float* src = (bb < 256) ? Whh : g_Wd;
        unsigned char* dst = (bb < 256) ? g_WTe : g_WTd;
        int b2 = bb & 255;
        int chunk = b2 & 7, ntile = b2 >> 3;
        int rr = tid >> 2, q = tid & 3;
        int joct = rr >> 5, rem = rr & 31;
        int gate = rem >> 3, j7 = rem & 7;
        int srow = gate * DM + ntile * 16 + joct * 8 + j7;
        unsigned char* d0 = dst + ((size_t)(ntile * 8 + chunk) * 2) * WIMG;
        #pragma unroll
        for (int c = 0; c < 18; c++) {
            int col = q * 18 + c;
            if (col < 64)
                store_split(d0, WIMG, (size_t)rr * 144 + col * 2,
                            src[(size_t)srow * DM + chunk * 64 + col]);
        }
    }
}

// ---------------- init ----------------------------------------------------------
__global__ __launch_bounds__(256) void init_kernel() {
    int i = blockIdx.x * 256 + threadIdx.x;
    if (i < (int)(sizeof(g_Hbf) / 4)) ((uint32_t*)g_Hbf)[i] = 0u;
    if (i < NSTEP * 4) g_bar[i] = 0u;
}

// ---------------- gx = xnorm @ Wih^T via HMMA split ----------------------------
#define GXSTAGE 55296
#define GX_SMEM (2*GXSTAGE)
__global__ void __launch_bounds__(256, 1) gxmma_kernel() {
    extern __shared__ unsigned char smem[];
    const int tid = threadIdx.x;
    const int w = tid >> 5, lane = tid & 31;
    const int n0 = blockIdx.x * 64;
    const int m0 = blockIdx.y * 128;
    uint32_t sbase = smem_u32(smem);
    float acc[8][4];
    #pragma unroll
    for (int f = 0; f < 8; f++)
        #pragma unroll
        for (int r = 0; r < 4; r++) acc[f][r] = 0.f;

    const uint32_t aoff = (uint32_t)((w * 16 + (lane & 15)) * 144 + (lane >> 4) * 16);
    const uint32_t boff = (uint32_t)(((((lane >> 4) & 1) * 8) + (lane & 7)) * 144 + ((lane >> 3) & 1) * 16);
    const unsigned char* Bbase = g_WIe + ((size_t)blockIdx.x * 6 * 2) * WIMG;

    auto issue = [&](int chunk, int buf) {
        uint32_t sb = sbase + buf * GXSTAGE;
        #pragma unroll
        for (int i = 0; i < 14; i++) {
            int idx = tid + i * 256;
            if (idx >= 3456) break;
            uint32_t dst; const unsigned char* src;
            if (idx < 2304) {
                int sp = idx / 1152; int off = (idx - sp * 1152) * 16;
                dst = sb + sp * 18432 + off;
                src = g_Xbf + (size_t)(chunk * 2 + sp) * XIMG + (size_t)m0 * 144 + off;
            } else {
                int j = idx - 2304; int sp = j / 576; int off = (j - sp * 576) * 16;
                dst = sb + 36864 + sp * 9216 + off;
                src = Bbase + (size_t)(chunk * 2 + sp) * WIMG + off;
            }
            cpasync16(dst, src);
        }
        CP_COMMIT();
    };

    issue(0, 0); issue(1, 1);
    #pragma unroll 1
    for (int c = 0; c < 6; c++) {
        if (c < 5) { CP_WAIT(1); } else { CP_WAIT(0); }
        __syncthreads();
        uint32_t st = sbase + (c & 1) * GXSTAGE;
        uint32_t sAhi = st, sAlo = st + 18432, sWhi = st + 36864, sWlo = st + 46080;
        #pragma unroll
        for (int kf = 0; kf < 4; kf++) {
            uint32_t ah[4], al[4], bh[4][4], bl[4][4];
            ldsm4(ah, sAhi + aoff + kf * 32);
            ldsm4(al, sAlo + aoff + kf * 32);
            #pragma unroll
            for (int ng = 0; ng < 4; ng++) {
                ldsm4(bh[ng], sWhi + boff + ng * 2304 + kf * 32);
                ldsm4(bl[ng], sWlo + boff + ng * 2304 + kf * 32);
            }
            #pragma unroll
            for (int ng = 0; ng < 4; ng++) { mma16816(acc[2*ng], ah, bh[ng]); mma16816(acc[2*ng+1], ah, bh[ng]+2); }
            #pragma unroll
            for (int ng = 0; ng < 4; ng++) { mma16816(acc[2*ng], ah, bl[ng]); mma16816(acc[2*ng+1], ah, bl[ng]+2); }
            #pragma unroll
            for (int ng = 0; ng < 4; ng++) { mma16816(acc[2*ng], al, bh[ng]); mma16816(acc[2*ng+1], al, bh[ng]+2); }
        }
        __syncthreads();
        if (c + 2 < 6) issue(c + 2, c & 1);
    }
    #pragma unroll
    for (int f = 0; f < 8; f++) {
        int n = n0 + (f >> 1) * 16 + (f & 1) * 8 + (lane & 3) * 2;
        #pragma unroll
        for (int rowi = 0; rowi < 2; rowi++) {
            int m = m0 + w * 16 + (lane >> 2) + rowi * 8;
            *(float2*)&g_Gx[(size_t)m * G4 + n] = make_float2(acc[f][rowi*2], acc[f][rowi*2+1]);
        }
    }
}

// ---------------- persistent LSTM kernel (bf16 3-term, 4-stage ring) -----------
#define WCACHE_B 147456
#define ABUF_B   18432
#define PERSIST_SMEM (WCACHE_B + 4*ABUF_B)     // 221184

__global__ void __launch_bounds__(256, 1) persist_kernel(const float* __restrict__ gx,
                                                         const float* __restrict__ benc,
                                                         const float* __restrict__ bd) {
    extern __shared__ unsigned char smem[];
    const int tid = threadIdx.x;
    const int w = tid >> 5, lane = tid & 31;
    const int wr = w & 3, wc = w >> 2;
    const int ntile = blockIdx.x, mq = blockIdx.y;
    uint32_t sbase = smem_u32(smem);
    uint32_t Wc = sbase;
    uint32_t Ab = sbase + WCACHE_B;

    const uint32_t aoff = (uint32_t)((wr * 16 + (lane & 15)) * 144 + (lane >> 4) * 16);
    const uint32_t boff = (uint32_t)((wc * 32 + ((lane >> 4) & 1) * 8 + (lane & 7)) * 144 + ((lane >> 3) & 1) * 16);

    const unsigned char* WEsrc = g_WTe + ((size_t)(ntile * 8) * 2) * WIMG;
    const unsigned char* WDsrc = g_WTd + ((size_t)(ntile * 8) * 2) * WIMG;

    auto loadW = [&](const unsigned char* src) {
        #pragma unroll 4
        for (int i = 0; i < 36; i++) {
            int idx = tid + i * 256;
            int img = idx / 576;
            int off = (idx - img * 576) * 16;
            cpasync16(Wc + img * 9216 + off, src + (size_t)img * WIMG + off);
        }
        CP_COMMIT();
    };
    auto loadA = [&](const unsigned char* Apar, int chunk, int buf) {
        #pragma unroll
        for (int i = 0; i < 5; i++) {
            int idx = tid + i * 256;
            if (idx < 1152) {
                int split = idx / 576;
                int off = (idx - split * 576) * 16;
                cpasync16(Ab + buf * ABUF_B + split * 9216 + off,
                          Apar + (size_t)(chunk * 2 + split) * AIMG + mq * 9216 + off);
            }
        }
        CP_COMMIT();
    };

    const int j0 = ntile * 16 + wc * 8 + (lane & 3) * 2;
    const int bbase = mq * 64 + wr * 16 + (lane >> 2);
    const int chunkA = ntile >> 2;
    const size_t colOff = (size_t)((ntile & 3) * 16 + wc * 8 + (lane & 3) * 2) * 2;

    float bi[4][2];
    #pragma unroll
    for (int g = 0; g < 4; g++) { bi[g][0] = benc[g * DM + j0]; bi[g][1] = benc[g * DM + j0 + 1]; }
    float creg[4] = {0.f, 0.f, 0.f, 0.f};

    loadW(WEsrc);
    CP_WAIT(0);
    __syncthreads();

    for (int s = 0; s < NSTEP; s++) {
        const bool enc = (s < TSEQ);
        if (s == TSEQ) {
            __syncthreads();
            loadW(WDsrc);
            #pragma unroll
            for (int g = 0; g < 4; g++) { bi[g][0] = bd[g * DM + j0]; bi[g][1] = bd[g * DM + j0 + 1]; }
            CP_WAIT(0);
            __syncthreads();
        }
        const int par = s & 1;
        const unsigned char* Apar = g_Hbf + (size_t)(par * 16) * AIMG;

        float pr[16];
        if (enc) {
            #pragma unroll
            for (int rowi = 0; rowi < 2; rowi++) {
                const float* gr = gx + ((size_t)(bbase + rowi * 8) * TSEQ + s) * G4;
                #pragma unroll
                for (int g = 0; g < 4; g++) {
                    float2 v = *(const float2*)&gr[g * DM + j0];
                    pr[rowi * 8 + g * 2]     = v.x;
                    pr[rowi * 8 + g * 2 + 1] = v.y;
                }
            }
        }

        float acc[4][4];
        #pragma unroll
        for (int g = 0; g < 4; g++)
            #pragma unroll
            for (int r = 0; r < 4; r++) acc[g][r] = 0.f;

        loadA(Apar, 0, 0); loadA(Apar, 1, 1); loadA(Apar, 2, 2);
        #pragma unroll 1
        for (int c = 0; c < 8; c++) {
            if (c + 3 < 8) { loadA(Apar, c + 3, (c + 3) & 3); CP_WAIT(3); }
            else if (c == 5) { CP_WAIT(2); }
            else if (c == 6) { CP_WAIT(1); }
            else             { CP_WAIT(0); }
            __syncthreads();
            uint32_t at = Ab + (c & 3) * ABUF_B;
            uint32_t sAhi = at, sAlo = at + 9216;
            uint32_t wt = Wc + c * 18432;
            uint32_t sWhi = wt, sWlo = wt + 9216;
            #pragma unroll
            for (int kf = 0; kf < 4; kf++) {
                uint32_t ah[4], al[4], bh0[4], bh1[4], bl0[4], bl1[4];
                ldsm4(ah,  sAhi + aoff + kf * 32);
                ldsm4(al,  sAlo + aoff + kf * 32);
                ldsm4(bh0, sWhi + boff + kf * 32);
                ldsm4(bh1, sWhi + boff + 2304 + kf * 32);
                ldsm4(bl0, sWlo + boff + kf * 32);
                ldsm4(bl1, sWlo + boff + 2304 + kf * 32);
                mma16816(acc[0], ah, bh0); mma16816(acc[1], ah, bh0 + 2);
                mma16816(acc[2], ah, bh1); mma16816(acc[3], ah, bh1 + 2);
                mma16816(acc[0], ah, bl0); mma16816(acc[1], ah, bl0 + 2);
                mma16816(acc[2], ah, bl1); mma16816(acc[3], ah, bl1 + 2);
                mma16816(acc[0], al, bh0); mma16816(acc[1], al, bh0 + 2);
                mma16816(acc[2], al, bh1); mma16816(acc[3], al, bh1 + 2);
            }
            __syncthreads();
        }

        // ---- epilogue ----
        unsigned char* imgHi = g_Hbf + (size_t)(((par ^ 1) * 8 + chunkA) * 2) * AIMG;
        unsigned char* imgLo = imgHi + AIMG;
        unsigned char* decHi = nullptr;
        if (s >= TSEQ - 1) {
            int d = s - (TSEQ - 1);
            decHi = g_Dbf + (size_t)((d * 8 + chunkA) * 2) * AIMG;
        }

        #pragma unroll
        for (int rowi = 0; rowi < 2; rowi++) {
            int b = bbase + rowi * 8;
            float h2[2];
            #pragma unroll
            for (int cp = 0; cp < 2; cp++) {
                float gi = acc[0][rowi * 2 + cp] + bi[0][cp];
                float gf = acc[1][rowi * 2 + cp] + bi[1][cp];
                float gg = acc[2][rowi * 2 + cp] + bi[2][cp];
                float go = acc[3][rowi * 2 + cp] + bi[3][cp];
                if (enc) {
                    gi += pr[rowi * 8 + 0 + cp];
                    gf += pr[rowi * 8 + 2 + cp];
                    gg += pr[rowi * 8 + 4 + cp];
                    go += pr[rowi * 8 + 6 + cp];
                }
                float cn = sigf(gf) * creg[rowi * 2 + cp] + sigf(gi) * tanhf(gg);
                float hn = sigf(go) * tanhf(cn);
                creg[rowi * 2 + cp] = cn;
                h2[cp] = hn;
            }
            uint32_t hw, lw;
            bfsplit2(h2[0], h2[1], hw, lw);
            size_t off = (size_t)b * 144 + colOff;
            *(uint32_t*)(imgHi + off) = hw;
            *(uint32_t*)(imgLo + off) = lw;
            if (decHi) {
                *(uint32_t*)(decHi + off) = hw;
                *(uint32_t*)(decHi + AIMG + off) = lw;
            }
        }

        // ---- per-mq step barrier ----
        if (s < NSTEP - 1) {
            __syncthreads();
            if (tid == 0) {
                __threadfence();
                unsigned* p = &g_bar[s * 4 + mq];
                unsigned prev = atomicAdd(p, 1u);
                if (prev != 31u) {
                    unsigned v;
                    do {
                        asm volatile("ld.acquire.gpu.u32 %0, [%1];" : "=r"(v) : "l"(p) : "memory");
                    } while (v < 32u);
                }
            }
            __syncthreads();
        }
    }
}

// ---------------- out: Y = Dbf @ Wp^T via HMMA, denormalize, scatter -----------
#define OSTAGE 55296
#define OUT_SMEM (2*OSTAGE)
__global__ void __launch_bounds__(256, 1) outmma_kernel(const float* __restrict__ bp,
                                                        float* __restrict__ out) {
    extern __shared__ unsigned char smem[];
    const int tid = threadIdx.x;
    const int w = tid >> 5, lane = tid & 31;
    const int ntile = blockIdx.x;        // 0..5
    const int mt = blockIdx.y;           // 0..191
    const int d = mt >> 1, half = mt & 1;
    const int m0 = half * 128;
    uint32_t sbase = smem_u32(smem);
    float acc[8][4];
    #pragma unroll
    for (int f = 0; f < 8; f++)
        #pragma unroll
        for (int r = 0; r < 4; r++) acc[f][r] = 0.f;

    const uint32_t aoff = (uint32_t)((w * 16 + (lane & 15)) * 144 + (lane >> 4) * 16);
    const uint32_t boff = (uint32_t)(((((lane >> 4) & 1) * 8) + (lane & 7)) * 144 + ((lane >> 3) & 1) * 16);
    const unsigned char* Abase = g_Dbf + (size_t)(d * 16) * AIMG;
    const unsigned char* Bbase = g_WPe + ((size_t)(ntile * 8) * 2) * WIMG;

    auto issue = [&](int chunk, int buf) {
        uint32_t sb = sbase + buf * OSTAGE;
        #pragma unroll
        for (int i = 0; i < 14; i++) {
            int idx = tid + i * 256;
            if (idx >= 3456) break;
            uint32_t dst; const unsigned char* src;
            if (idx < 2304) {
                int sp = idx / 1152; int off = (idx - sp * 1152) * 16;
                dst = sb + sp * 18432 + off;
                src = Abase + (size_t)(chunk * 2 + sp) * AIMG + (size_t)m0 * 144 + off;
            } else {
                int j = idx - 2304; int sp = j / 576; int off = (j - sp * 576) * 16;
                dst = sb + 36864 + sp * 9216 + off;
                src = Bbase + (size_t)(chunk * 2 + sp) * WIMG + off;
            }
            cpasync16(dst, src);
        }
        CP_COMMIT();
    };

    issue(0, 0); issue(1, 1);
    #pragma unroll 1
    for (int c = 0; c < 8; c++) {
        if (c < 7) { CP_WAIT(1); } else { CP_WAIT(0); }
        __syncthreads();
        uint32_t st = sbase + (c & 1) * OSTAGE;
        uint32_t sAhi = st, sAlo = st + 18432, sWhi = st + 36864, sWlo = st + 46080;
        #pragma unroll
        for (int kf = 0; kf < 4; kf++) {
            uint32_t ah[4], al[4], bh[4][4], bl[4][4];
            ldsm4(ah, sAhi + aoff + kf * 32);
            ldsm4(al, sAlo + aoff + kf * 32);
            #pragma unroll
            for (int ng = 0; ng < 4; ng++) {
                ldsm4(bh[ng], sWhi + boff + ng * 2304 + kf * 32);
                ldsm4(bl[ng], sWlo + boff + ng * 2304 + kf * 32);
            }
            #pragma unroll
            for (int ng = 0; ng < 4; ng++) { mma16816(acc[2*ng], ah, bh[ng]); mma16816(acc[2*ng+1], ah, bh[ng]+2); }
            #pragma unroll
            for (int ng = 0; ng < 4; ng++) { mma16816(acc[2*ng], ah, bl[ng]); mma16816(acc[2*ng+1], ah, bl[ng]+2); }
            #pragma unroll
            for (int ng = 0; ng < 4; ng++) { mma16816(acc[2*ng], al, bh[ng]); mma16816(acc[2*ng+1], al, bh[ng]+2); }
        }
        __syncthreads();
        if (c + 2 < 8) issue(c + 2, c & 1);
    }
    #pragma unroll
    for (int f = 0; f < 8; f++) {
        int gn = ntile * 64 + (f >> 1) * 16 + (f & 1) * 8 + (lane & 3) * 2;
        #pragma unroll
        for (int rowi = 0; rowi < 2; rowi++) {
            int b = m0 + w * 16 + (lane >> 2) + rowi * 8;
            #pragma unroll
            for (int cp = 0; cp < 2; cp++) {
                int n = gn + cp;
                if (n < CIN) {
                    int bc = b * CIN + n;
                    float y = acc[f][rowi * 2 + cp] + bp[n];
                    out[(size_t)b * PRED * CIN + (size_t)d * CIN + n] =
                        y * g_std[bc] + g_mean[bc];
                }
            }
        }
    }
}

// ---------------- host launcher ------------------------------------------------
extern "C" void kernel_launch(void* const* d_in, const int* in_sizes, int n_in,
                              void* d_out, int out_size) {
    const float* x   = (const float*)d_in[0];
    const float* Wih = (const float*)d_in[1];
    const float* Whh = (const float*)d_in[2];
    const float* bih = (const float*)d_in[3];
    const float* bhh = (const float*)d_in[4];
    const float* Wp  = (const float*)d_in[5];
    const float* bp  = (const float*)d_in[6];
    float* out = (float*)d_out;

    float *gx, *bd, *benc;
    cudaGetSymbolAddress((void**)&gx,   g_Gx);
    cudaGetSymbolAddress((void**)&bd,   g_bd);
    cudaGetSymbolAddress((void**)&benc, g_benc);

    cudaFuncSetAttribute(persist_kernel, cudaFuncAttributeMaxDynamicSharedMemorySize, PERSIST_SMEM);
    cudaFuncSetAttribute(gxmma_kernel, cudaFuncAttributeMaxDynamicSharedMemorySize, GX_SMEM);
    cudaFuncSetAttribute(outmma_kernel, cudaFuncAttributeMaxDynamicSharedMemorySize, OUT_SMEM);

    // launch order fixed so persist is launch #6 (ncu -s 5 -c 1 profiles it)
    prep0_kernel<<<329, 256>>>(x, bih, bhh, Wih, bp);                       // 1
    wd_kernel<<<dim3(DM / 64, G4 / 64), 256>>>(Wih, Wp, Whh);               // 2
    megasplit_kernel<<<XBLKS + 192 + 48 + 512, 256>>>(x, Wih, Wp, Whh);     // 3
    init_kernel<<<((int)(sizeof(g_Hbf) / 4) + 255) / 256, 256>>>();         // 4
    gxmma_kernel<<<dim3(32, 192), 256, GX_SMEM>>>();                        // 5
    persist_kernel<<<dim3(32, 4), 256, PERSIST_SMEM>>>(gx, benc, bd);       // 6
    outmma_kernel<<<dim3(6, 192), 256, OUT_SMEM>>>(bp, out);                // 7
    (void)in_sizes; (void)n_in; (void)out_size;
}

// round 10
// speedup vs baseline: 1.8561x; 1.3957x over previous
#include <cuda_runtime.h>
#include <cuda_bf16.h>
#include <math.h>
#include <stdint.h>

#define BATCH 256
#define TSEQ  96
#define PRED  96
#define CIN   321
#define DM    512
#define G4    2048
#define HD    (BATCH*DM)
#define NSTEP (TSEQ+PRED-1)     // 191

#define AIMG  36864u            // bf16 image: 256 rows x 144 B per (chunk,split)
#define WIMG  9216u             // bf16 W image: 64 rows x 144 B
#define XIMG  (24576u*144u)

// ---------------- device scratch ----------------------------------------------
__device__ float g_mean[BATCH*CIN];
__device__ float g_std [BATCH*CIN];
__device__ float g_istd[BATCH*CIN];
__device__ float g_Gx  [(size_t)BATCH*TSEQ*G4];
__device__ float g_Wd  [G4*DM];
__device__ float g_bd  [G4];
__device__ float g_benc[G4];
__device__ unsigned g_bar[NSTEP+1];
// bf16 hidden images: [par2][chunk8][split2][256][72]
__device__ __align__(1024) unsigned char g_Hbf[2*8*2*AIMG];
// decoder hidden bf16 split images: [d96][chunk8][split2][256][72]
__device__ __align__(1024) unsigned char g_Dbf[(size_t)96*8*2*AIMG];
// recurrent W images: [ntile32][chunk8][split2][64][72]
__device__ __align__(1024) unsigned char g_WTe[32*8*2*WIMG];
__device__ __align__(1024) unsigned char g_WTd[32*8*2*WIMG];
// gx operand images
__device__ __align__(1024) unsigned char g_Xbf[6*2*XIMG];
__device__ __align__(1024) unsigned char g_WIe[32*6*2*WIMG];
// Wp images for out: [ntile6][chunk8][split2][64][72]
__device__ __align__(1024) unsigned char g_WPe[6*8*2*WIMG];

// ---------------- helpers ------------------------------------------------------
__device__ __forceinline__ float sigf(float x) { return 1.f / (1.f + expf(-x)); }

__device__ __forceinline__ uint32_t smem_u32(const void* p) {
    uint32_t a;
    asm("{ .reg .u64 t; cvta.to.shared.u64 t, %1; cvt.u32.u64 %0, t; }" : "=r"(a) : "l"(p));
    return a;
}
__device__ __forceinline__ void cpasync16(uint32_t dst, const void* src) {
    asm volatile("cp.async.cg.shared.global [%0], [%1], 16;" :: "r"(dst), "l"(src) : "memory");
}
#define CP_COMMIT() asm volatile("cp.async.commit_group;" ::: "memory")
#define CP_WAIT(N)  asm volatile("cp.async.wait_group %0;" :: "n"(N) : "memory")

__device__ __forceinline__ void ldsm4(uint32_t* r, uint32_t addr) {
    asm volatile("ldmatrix.sync.aligned.m8n8.x4.shared.b16 {%0,%1,%2,%3}, [%4];"
        : "=r"(r[0]), "=r"(r[1]), "=r"(r[2]), "=r"(r[3]) : "r"(addr));
}
__device__ __forceinline__ void mma16816(float* d, const uint32_t* a, const uint32_t* b) {
    asm volatile("mma.sync.aligned.m16n8k16.row.col.f32.bf16.bf16.f32 "
        "{%0,%1,%2,%3}, {%4,%5,%6,%7}, {%8,%9}, {%0,%1,%2,%3};"
        : "+f"(d[0]), "+f"(d[1]), "+f"(d[2]), "+f"(d[3])
        : "r"(a[0]), "r"(a[1]), "r"(a[2]), "r"(a[3]), "r"(b[0]), "r"(b[1]));
}
__device__ __forceinline__ void bfsplit2(float a, float b, uint32_t& hw, uint32_t& lw) {
    __nv_bfloat16 h0 = __float2bfloat16(a), h1 = __float2bfloat16(b);
    float r0 = a - __bfloat162float(h0), r1 = b - __bfloat162float(h1);
    __nv_bfloat16 l0 = __float2bfloat16(r0), l1 = __float2bfloat16(r1);
    hw = (uint32_t)__bfloat16_as_ushort(h0) | ((uint32_t)__bfloat16_as_ushort(h1) << 16);
    lw = (uint32_t)__bfloat16_as_ushort(l0) | ((uint32_t)__bfloat16_as_ushort(l1) << 16);
}

// ---------------- stats --------------------------------------------------------
__global__ __launch_bounds__(256) void stats_kernel(const float* __restrict__ x) {
    int idx = blockIdx.x * 256 + threadIdx.x;
    if (idx >= BATCH * CIN) return;
    int b = idx / CIN, ch = idx % CIN;
    float s = 0.f, ss = 0.f;
    const float* p = x + (size_t)b * TSEQ * CIN + ch;
    #pragma unroll 4
    for (int t = 0; t < TSEQ; t++) { float v = p[t * CIN]; s += v; ss += v * v; }
    float mean = s * (1.f / TSEQ);
    float var = ss * (1.f / TSEQ) - mean * mean;
    if (var < 0.f) var = 0.f;
    float sd = sqrtf(var + 1e-5f);
    g_mean[idx] = mean; g_std[idx] = sd; g_istd[idx] = 1.f / sd;
}

// ---------------- bias fold ----------------------------------------------------
__global__ __launch_bounds__(256) void bias_kernel(const float* __restrict__ bih,
                                                   const float* __restrict__ bhh,
                                                   const float* __restrict__ Wih,
                                                   const float* __restrict__ bp) {
    int n = blockIdx.x * 256 + threadIdx.x;
    if (n >= G4) return;
    float be = bih[n] + bhh[n];
    float s = 0.f;
    const float* w = Wih + (size_t)n * CIN;
    for (int j = 0; j < CIN; j++) s += w[j] * bp[j];
    g_benc[n] = be;
    g_bd[n] = be + s;
}

// ---------------- Wd = Whh + Wih @ Wp ------------------------------------------
__global__ __launch_bounds__(256) void wd_kernel(const float* __restrict__ Wih,
                                                 const float* __restrict__ Wp,
                                                 const float* __restrict__ Whh) {
    __shared__ float As[64 * 17];
    __shared__ float Bs[16 * 65];
    int tid = threadIdx.x;
    int n0 = blockIdx.x * 64;
    int m0 = blockIdx.y * 64;
    int tr = tid >> 4, tc = tid & 15;
    float acc[4][4] = {};
    for (int j0 = 0; j0 < CIN; j0 += 16) {
        #pragma unroll
        for (int i = 0; i < 4; i++) {
            int l = tid + 256 * i;
            int mr = l >> 4, jj = l & 15;
            int j = j0 + jj;
            As[mr * 17 + jj] = (j < CIN) ? Wih[(size_t)(m0 + mr) * CIN + j] : 0.f;
        }
        #pragma unroll
        for (int i = 0; i < 4; i++) {
            int l = tid + 256 * i;
            int jj = l >> 6, nr = l & 63;
            int j = j0 + jj;
            Bs[jj * 65 + nr] = (j < CIN) ? Wp[(size_t)j * DM + n0 + nr] : 0.f;
        }
        __syncthreads();
        #pragma unroll
        for (int jj = 0; jj < 16; jj++) {
            float a[4], bb[4];
            #pragma unroll
            for (int r = 0; r < 4; r++) a[r] = As[(tr * 4 + r) * 17 + jj];
            #pragma unroll
            for (int cc = 0; cc < 4; cc++) bb[cc] = Bs[jj * 65 + tc * 4 + cc];
            #pragma unroll
            for (int r = 0; r < 4; r++)
                #pragma unroll
                for (int cc = 0; cc < 4; cc++) acc[r][cc] += a[r] * bb[cc];
        }
        __syncthreads();
    }
    #pragma unroll
    for (int r = 0; r < 4; r++) {
        int m = m0 + tr * 4 + r;
        #pragma unroll
        for (int cc = 0; cc < 4; cc++) {
            int n = n0 + tc * 4 + cc;
            g_Wd[(size_t)m * DM + n] = Whh[(size_t)m * DM + n] + acc[r][cc];
        }
    }
}

// ---------------- recurrent W image builder ------------------------------------
__global__ __launch_bounds__(256) void wsplit_kernel(const float* __restrict__ src,
                                                     unsigned char* __restrict__ dst) {
    int chunk = blockIdx.x;
    int ntile = blockIdx.y;
    int tid = threadIdx.x;
    int rr = tid >> 2;
    int q  = tid & 3;
    int joct = rr >> 5, rem = rr & 31;
    int gate = rem >> 3, j7 = rem & 7;
    int srow = gate * DM + ntile * 16 + joct * 8 + j7;
    unsigned char* d0 = dst + ((size_t)(ntile * 8 + chunk) * 2) * WIMG;
    #pragma unroll
    for (int c = 0; c < 18; c++) {
        int col = q * 18 + c;
        float v = (col < 64) ? src[(size_t)srow * DM + chunk * 64 + col] : 0.f;
        __nv_bfloat16 hb = __float2bfloat16(v);
        float rem2 = v - __bfloat162float(hb);
        __nv_bfloat16 lb = __float2bfloat16(rem2);
        size_t off = (size_t)rr * 144 + col * 2;
        *(__nv_bfloat16*)(d0 + off)        = hb;
        *(__nv_bfloat16*)(d0 + WIMG + off) = lb;
    }
}

// ---------------- Wih image builder for gx -------------------------------------
__global__ __launch_bounds__(256) void wihsplit_kernel(const float* __restrict__ Wih) {
    int chunk = blockIdx.x;
    int ntile = blockIdx.y;
    int tid = threadIdx.x;
    int rr = tid >> 2;
    int q  = tid & 3;
    int srow = ntile * 64 + rr;
    unsigned char* d0 = g_WIe + ((size_t)(ntile * 6 + chunk) * 2) * WIMG;
    #pragma unroll
    for (int c = 0; c < 18; c++) {
        int col = q * 18 + c;
        int k = chunk * 64 + col;
        float v = (col < 64 && k < CIN) ? Wih[(size_t)srow * CIN + k] : 0.f;
        __nv_bfloat16 hb = __float2bfloat16(v);
        float rem2 = v - __bfloat162float(hb);
        __nv_bfloat16 lb = __float2bfloat16(rem2);
        size_t off = (size_t)rr * 144 + col * 2;
        *(__nv_bfloat16*)(d0 + off)        = hb;
        *(__nv_bfloat16*)(d0 + WIMG + off) = lb;
    }
}

// ---------------- Wp image builder for out -------------------------------------
__global__ __launch_bounds__(256) void wpsplit_kernel(const float* __restrict__ Wp) {
    int chunk = blockIdx.x;   // 0..7
    int ntile = blockIdx.y;   // 0..5
    int tid = threadIdx.x;
    int rr = tid >> 2;
    int q  = tid & 3;
    int n = ntile * 64 + rr;
    unsigned char* d0 = g_WPe + ((size_t)(ntile * 8 + chunk) * 2) * WIMG;
    #pragma unroll
    for (int c = 0; c < 18; c++) {
        int col = q * 18 + c;
        int k = chunk * 64 + col;
        float v = (col < 64 && n < CIN) ? Wp[(size_t)n * DM + k] : 0.f;
        __nv_bfloat16 hb = __float2bfloat16(v);
        float rem2 = v - __bfloat162float(hb);
        __nv_bfloat16 lb = __float2bfloat16(rem2);
        size_t off = (size_t)rr * 144 + col * 2;
        *(__nv_bfloat16*)(d0 + off)        = hb;
        *(__nv_bfloat16*)(d0 + WIMG + off) = lb;
    }
}

// ---------------- x normalize+split images -------------------------------------
__global__ __launch_bounds__(256) void xsplit_kernel(const float* __restrict__ x) {
    int idx = blockIdx.x * 256 + threadIdx.x;
    if (idx >= BATCH * TSEQ * CIN) return;
    int m = idx / CIN, k = idx - m * CIN;
    int b = m / TSEQ;
    int bc = b * CIN + k;
    float v = (x[idx] - g_mean[bc]) * g_istd[bc];
    __nv_bfloat16 hb = __float2bfloat16(v);
    float rem = v - __bfloat162float(hb);
    __nv_bfloat16 lb = __float2bfloat16(rem);
    int chunk = k >> 6, col = k & 63;
    size_t offh = ((size_t)(chunk * 2) * 24576 + m) * 144 + col * 2;
    *(__nv_bfloat16*)(g_Xbf + offh)        = hb;
    *(__nv_bfloat16*)(g_Xbf + offh + XIMG) = lb;
}

// ---------------- init ----------------------------------------------------------
__global__ __launch_bounds__(256) void init_kernel() {
    int i = blockIdx.x * 256 + threadIdx.x;
    if (i < (int)(sizeof(g_Hbf) / 4)) ((uint32_t*)g_Hbf)[i] = 0u;
    if (i <= NSTEP) g_bar[i] = 0u;
}

// ---------------- gx = xnorm @ Wih^T via HMMA split ----------------------------
#define GXSTAGE 55296
#define GX_SMEM (2*GXSTAGE)
__global__ void __launch_bounds__(256, 1) gxmma_kernel() {
    extern __shared__ unsigned char smem[];
    const int tid = threadIdx.x;
    const int w = tid >> 5, lane = tid & 31;
    const int n0 = blockIdx.x * 64;
    const int m0 = blockIdx.y * 128;
    uint32_t sbase = smem_u32(smem);
    float acc[8][4];
    #pragma unroll
    for (int f = 0; f < 8; f++)
        #pragma unroll
        for (int r = 0; r < 4; r++) acc[f][r] = 0.f;

    const uint32_t aoff = (uint32_t)((w * 16 + (lane & 15)) * 144 + (lane >> 4) * 16);
    const uint32_t boff = (uint32_t)(((((lane >> 4) & 1) * 8) + (lane & 7)) * 144 + ((lane >> 3) & 1) * 16);
    const unsigned char* Bbase = g_WIe + ((size_t)blockIdx.x * 6 * 2) * WIMG;

    auto issue = [&](int chunk, int buf) {
        uint32_t sb = sbase + buf * GXSTAGE;
        #pragma unroll
        for (int i = 0; i < 14; i++) {
            int idx = tid + i * 256;
            if (idx >= 3456) break;
            uint32_t dst; const unsigned char* src;
            if (idx < 2304) {
                int sp = idx / 1152; int off = (idx - sp * 1152) * 16;
                dst = sb + sp * 18432 + off;
                src = g_Xbf + (size_t)(chunk * 2 + sp) * XIMG + (size_t)m0 * 144 + off;
            } else {
                int j = idx - 2304; int sp = j / 576; int off = (j - sp * 576) * 16;
                dst = sb + 36864 + sp * 9216 + off;
                src = Bbase + (size_t)(chunk * 2 + sp) * WIMG + off;
            }
            cpasync16(dst, src);
        }
        CP_COMMIT();
    };

    issue(0, 0); issue(1, 1);
    #pragma unroll 1
    for (int c = 0; c < 6; c++) {
        if (c < 5) { CP_WAIT(1); } else { CP_WAIT(0); }
        __syncthreads();
        uint32_t st = sbase + (c & 1) * GXSTAGE;
        uint32_t sAhi = st, sAlo = st + 18432, sWhi = st + 36864, sWlo = st + 46080;
        #pragma unroll
        for (int kf = 0; kf < 4; kf++) {
            uint32_t ah[4], al[4], bh[4][4], bl[4][4];
            ldsm4(ah, sAhi + aoff + kf * 32);
            ldsm4(al, sAlo + aoff + kf * 32);
            #pragma unroll
            for (int ng = 0; ng < 4; ng++) {
                ldsm4(bh[ng], sWhi + boff + ng * 2304 + kf * 32);
                ldsm4(bl[ng], sWlo + boff + ng * 2304 + kf * 32);
            }
            #pragma unroll
            for (int ng = 0; ng < 4; ng++) { mma16816(acc[2*ng], ah, bh[ng]); mma16816(acc[2*ng+1], ah, bh[ng]+2); }
            #pragma unroll
            for (int ng = 0; ng < 4; ng++) { mma16816(acc[2*ng], ah, bl[ng]); mma16816(acc[2*ng+1], ah, bl[ng]+2); }
            #pragma unroll
            for (int ng = 0; ng < 4; ng++) { mma16816(acc[2*ng], al, bh[ng]); mma16816(acc[2*ng+1], al, bh[ng]+2); }
        }
        __syncthreads();
        if (c + 2 < 6) issue(c + 2, c & 1);
    }
    #pragma unroll
    for (int f = 0; f < 8; f++) {
        int n = n0 + (f >> 1) * 16 + (f & 1) * 8 + (lane & 3) * 2;
        #pragma unroll
        for (int rowi = 0; rowi < 2; rowi++) {
            int m = m0 + w * 16 + (lane >> 2) + rowi * 8;
            *(float2*)&g_Gx[(size_t)m * G4 + n] = make_float2(acc[f][rowi*2], acc[f][rowi*2+1]);
        }
    }
}

// ---------------- persistent LSTM kernel (bf16 3-term, R6 config) --------------
#define WCACHE_B 147456
#define ABUF_B   18432
#define PERSIST_SMEM (WCACHE_B + 3*ABUF_B)

__global__ void __launch_bounds__(256, 1) persist_kernel(const float* __restrict__ gx,
                                                         const float* __restrict__ benc,
                                                         const float* __restrict__ bd) {
    extern __shared__ unsigned char smem[];
    const int tid = threadIdx.x;
    const int w = tid >> 5, lane = tid & 31;
    const int wr = w & 3, wc = w >> 2;
    const int ntile = blockIdx.x, mq = blockIdx.y;
    uint32_t sbase = smem_u32(smem);
    uint32_t Wc = sbase;
    uint32_t Ab = sbase + WCACHE_B;

    const uint32_t aoff = (uint32_t)((wr * 16 + (lane & 15)) * 144 + (lane >> 4) * 16);
    const uint32_t boff = (uint32_t)((wc * 32 + ((lane >> 4) & 1) * 8 + (lane & 7)) * 144 + ((lane >> 3) & 1) * 16);

    const unsigned char* WEsrc = g_WTe + ((size_t)(ntile * 8) * 2) * WIMG;
    const unsigned char* WDsrc = g_WTd + ((size_t)(ntile * 8) * 2) * WIMG;

    auto loadW = [&](const unsigned char* src) {
        #pragma unroll 4
        for (int i = 0; i < 36; i++) {
            int idx = tid + i * 256;
            int img = idx / 576;
            int off = (idx - img * 576) * 16;
            cpasync16(Wc + img * 9216 + off, src + (size_t)img * WIMG + off);
        }
        CP_COMMIT();
    };
    auto loadA = [&](const unsigned char* Apar, int chunk, int buf) {
        #pragma unroll
        for (int i = 0; i < 5; i++) {
            int idx = tid + i * 256;
            if (idx < 1152) {
                int split = idx / 576;
                int off = (idx - split * 576) * 16;
                cpasync16(Ab + buf * ABUF_B + split * 9216 + off,
                          Apar + (size_t)(chunk * 2 + split) * AIMG + mq * 9216 + off);
            }
        }
        CP_COMMIT();
    };

    const int j0 = ntile * 16 + wc * 8 + (lane & 3) * 2;
    const int bbase = mq * 64 + wr * 16 + (lane >> 2);
    const int chunkA = ntile >> 2;
    const size_t colOff = (size_t)((ntile & 3) * 16 + wc * 8 + (lane & 3) * 2) * 2;

    float bi[4][2];
    #pragma unroll
    for (int g = 0; g < 4; g++) { bi[g][0] = benc[g * DM + j0]; bi[g][1] = benc[g * DM + j0 + 1]; }
    float creg[4] = {0.f, 0.f, 0.f, 0.f};

    loadW(WEsrc);
    CP_WAIT(0);
    __syncthreads();

    for (int s = 0; s < NSTEP; s++) {
        const bool enc = (s < TSEQ);
        if (s == TSEQ) {
            __syncthreads();
            loadW(WDsrc);
            #pragma unroll
            for (int g = 0; g < 4; g++) { bi[g][0] = bd[g * DM + j0]; bi[g][1] = bd[g * DM + j0 + 1]; }
            CP_WAIT(0);
            __syncthreads();
        }
        const int par = s & 1;
        const unsigned char* Apar = g_Hbf + (size_t)(par * 16) * AIMG;

        float pr[16];
        if (enc) {
            #pragma unroll
            for (int rowi = 0; rowi < 2; rowi++) {
                const float* gr = gx + ((size_t)(bbase + rowi * 8) * TSEQ + s) * G4;
                #pragma unroll
                for (int g = 0; g < 4; g++) {
                    float2 v = *(const float2*)&gr[g * DM + j0];
                    pr[rowi * 8 + g * 2]     = v.x;
                    pr[rowi * 8 + g * 2 + 1] = v.y;
                }
            }
        }

        float acc[4][4];
        #pragma unroll
        for (int g = 0; g < 4; g++)
            #pragma unroll
            for (int r = 0; r < 4; r++) acc[g][r] = 0.f;

        if (s > 0) {    // s==0: h=0, MMA result is all zeros — skip loads+MMA entirely
            loadA(Apar, 0, 0);
            loadA(Apar, 1, 1);
            #pragma unroll 1
            for (int c = 0; c < 8; c++) {
                if (c + 2 < 8) { loadA(Apar, c + 2, (c + 2) % 3); CP_WAIT(2); }
                else if (c == 6) { CP_WAIT(1); }
                else if (c == 7) { CP_WAIT(0); }
                __syncthreads();
                uint32_t at = Ab + (c % 3) * ABUF_B;
                uint32_t sAhi = at, sAlo = at + 9216;
                uint32_t wt = Wc + c * 18432;
                uint32_t sWhi = wt, sWlo = wt + 9216;
                #pragma unroll
                for (int kf = 0; kf < 4; kf++) {
                    uint32_t ah[4], al[4], bh0[4], bh1[4], bl0[4], bl1[4];
                    ldsm4(ah,  sAhi + aoff + kf * 32);
                    ldsm4(al,  sAlo + aoff + kf * 32);
                    ldsm4(bh0, sWhi + boff + kf * 32);
                    ldsm4(bh1, sWhi + boff + 2304 + kf * 32);
                    ldsm4(bl0, sWlo + boff + kf * 32);
                    ldsm4(bl1, sWlo + boff + 2304 + kf * 32);
                    mma16816(acc[0], ah, bh0); mma16816(acc[1], ah, bh0 + 2);
                    mma16816(acc[2], ah, bh1); mma16816(acc[3], ah, bh1 + 2);
                    mma16816(acc[0], ah, bl0); mma16816(acc[1], ah, bl0 + 2);
                    mma16816(acc[2], ah, bl1); mma16816(acc[3], ah, bl1 + 2);
                    mma16816(acc[0], al, bh0); mma16816(acc[1], al, bh0 + 2);
                    mma16816(acc[2], al, bh1); mma16816(acc[3], al, bh1 + 2);
                }
                __syncthreads();
            }
        }

        // ---- epilogue ----
        unsigned char* imgHi = g_Hbf + (size_t)(((par ^ 1) * 8 + chunkA) * 2) * AIMG;
        unsigned char* imgLo = imgHi + AIMG;
        unsigned char* decHi = nullptr;
        if (s >= TSEQ - 1) {
            int d = s - (TSEQ - 1);
            decHi = g_Dbf + (size_t)((d * 8 + chunkA) * 2) * AIMG;
        }

        #pragma unroll
        for (int rowi = 0; rowi < 2; rowi++) {
            int b = bbase + rowi * 8;
            float h2[2];
            #pragma unroll
            for (int cp = 0; cp < 2; cp++) {
                float gi = acc[0][rowi * 2 + cp] + bi[0][cp];
                float gf = acc[1][rowi * 2 + cp] + bi[1][cp];
                float gg = acc[2][rowi * 2 + cp] + bi[2][cp];
                float go = acc[3][rowi * 2 + cp] + bi[3][cp];
                if (enc) {
                    gi += pr[rowi * 8 + 0 + cp];
                    gf += pr[rowi * 8 + 2 + cp];
                    gg += pr[rowi * 8 + 4 + cp];
                    go += pr[rowi * 8 + 6 + cp];
                }
                float cn = sigf(gf) * creg[rowi * 2 + cp] + sigf(gi) * tanhf(gg);
                float hn = sigf(go) * tanhf(cn);
                creg[rowi * 2 + cp] = cn;
                h2[cp] = hn;
            }
            uint32_t hw, lw;
            bfsplit2(h2[0], h2[1], hw, lw);
            size_t off = (size_t)b * 144 + colOff;
            *(uint32_t*)(imgHi + off) = hw;
            *(uint32_t*)(imgLo + off) = lw;
            if (decHi) {
                *(uint32_t*)(decHi + off) = hw;
                *(uint32_t*)(decHi + AIMG + off) = lw;
            }
        }

        // ---- grid barrier (R6 form) ----
        if (s < NSTEP - 1) {
            __threadfence();
            __syncthreads();
            if (tid == 0) {
                unsigned prev = atomicAdd(&g_bar[s], 1u);
                if (prev != 127u) {
                    unsigned v;
                    unsigned* p = &g_bar[s];
                    do {
                        asm volatile("ld.acquire.gpu.u32 %0, [%1];" : "=r"(v) : "l"(p) : "memory");
                    } while (v < 128u);
                }
            }
            __syncthreads();
        }
    }
}

// ---------------- out: Y = Dbf @ Wp^T via HMMA, denormalize, scatter -----------
#define OSTAGE 55296
#define OUT_SMEM (2*OSTAGE)
__global__ void __launch_bounds__(256, 1) outmma_kernel(const float* __restrict__ bp,
                                                        float* __restrict__ out) {
    extern __shared__ unsigned char smem[];
    const int tid = threadIdx.x;
    const int w = tid >> 5, lane = tid & 31;
    const int ntile = blockIdx.x;        // 0..5
    const int mt = blockIdx.y;           // 0..191
    const int d = mt >> 1, half = mt & 1;
    const int m0 = half * 128;
    uint32_t sbase = smem_u32(smem);
    float acc[8][4];
    #pragma unroll
    for (int f = 0; f < 8; f++)
        #pragma unroll
        for (int r = 0; r < 4; r++) acc[f][r] = 0.f;

    const uint32_t aoff = (uint32_t)((w * 16 + (lane & 15)) * 144 + (lane >> 4) * 16);
    const uint32_t boff = (uint32_t)(((((lane >> 4) & 1) * 8) + (lane & 7)) * 144 + ((lane >> 3) & 1) * 16);
    const unsigned char* Abase = g_Dbf + (size_t)(d * 16) * AIMG;
    const unsigned char* Bbase = g_WPe + ((size_t)(ntile * 8) * 2) * WIMG;

    auto issue = [&](int chunk, int buf) {
        uint32_t sb = sbase + buf * OSTAGE;
        #pragma unroll
        for (int i = 0; i < 14; i++) {
            int idx = tid + i * 256;
            if (idx >= 3456) break;
            uint32_t dst; const unsigned char* src;
            if (idx < 2304) {
                int sp = idx / 1152; int off = (idx - sp * 1152) * 16;
                dst = sb + sp * 18432 + off;
                src = Abase + (size_t)(chunk * 2 + sp) * AIMG + (size_t)m0 * 144 + off;
            } else {
                int j = idx - 2304; int sp = j / 576; int off = (j - sp * 576) * 16;
                dst = sb + 36864 + sp * 9216 + off;
                src = Bbase + (size_t)(chunk * 2 + sp) * WIMG + off;
            }
            cpasync16(dst, src);
        }
        CP_COMMIT();
    };

    issue(0, 0); issue(1, 1);
    #pragma unroll 1
    for (int c = 0; c < 8; c++) {
        if (c < 7) { CP_WAIT(1); } else { CP_WAIT(0); }
        __syncthreads();
        uint32_t st = sbase + (c & 1) * OSTAGE;
        uint32_t sAhi = st, sAlo = st + 18432, sWhi = st + 36864, sWlo = st + 46080;
        #pragma unroll
        for (int kf = 0; kf < 4; kf++) {
            uint32_t ah[4], al[4], bh[4][4], bl[4][4];
            ldsm4(ah, sAhi + aoff + kf * 32);
            ldsm4(al, sAlo + aoff + kf * 32);
            #pragma unroll
            for (int ng = 0; ng < 4; ng++) {
                ldsm4(bh[ng], sWhi + boff + ng * 2304 + kf * 32);
                ldsm4(bl[ng], sWlo + boff + ng * 2304 + kf * 32);
            }
            #pragma unroll
            for (int ng = 0; ng < 4; ng++) { mma16816(acc[2*ng], ah, bh[ng]); mma16816(acc[2*ng+1], ah, bh[ng]+2); }
            #pragma unroll
            for (int ng = 0; ng < 4; ng++) { mma16816(acc[2*ng], ah, bl[ng]); mma16816(acc[2*ng+1], ah, bl[ng]+2); }
            #pragma unroll
            for (int ng = 0; ng < 4; ng++) { mma16816(acc[2*ng], al, bh[ng]); mma16816(acc[2*ng+1], al, bh[ng]+2); }
        }
        __syncthreads();
        if (c + 2 < 8) issue(c + 2, c & 1);
    }
    #pragma unroll
    for (int f = 0; f < 8; f++) {
        int gn = ntile * 64 + (f >> 1) * 16 + (f & 1) * 8 + (lane & 3) * 2;
        #pragma unroll
        for (int rowi = 0; rowi < 2; rowi++) {
            int b = m0 + w * 16 + (lane >> 2) + rowi * 8;
            #pragma unroll
            for (int cp = 0; cp < 2; cp++) {
                int n = gn + cp;
                if (n < CIN) {
                    int bc = b * CIN + n;
                    float y = acc[f][rowi * 2 + cp] + bp[n];
                    out[(size_t)b * PRED * CIN + (size_t)d * CIN + n] =
                        y * g_std[bc] + g_mean[bc];
                }
            }
        }
    }
}

// ---------------- host launcher ------------------------------------------------
extern "C" void kernel_launch(void* const* d_in, const int* in_sizes, int n_in,
                              void* d_out, int out_size) {
    const float* x   = (const float*)d_in[0];
    const float* Wih = (const float*)d_in[1];
    const float* Whh = (const float*)d_in[2];
    const float* bih = (const float*)d_in[3];
    const float* bhh = (const float*)d_in[4];
    const float* Wp  = (const float*)d_in[5];
    const float* bp  = (const float*)d_in[6];
    float* out = (float*)d_out;

    float *gx, *wd, *bd, *benc;
    unsigned char *wte, *wtd;
    cudaGetSymbolAddress((void**)&gx,   g_Gx);
    cudaGetSymbolAddress((void**)&wd,   g_Wd);
    cudaGetSymbolAddress((void**)&bd,   g_bd);
    cudaGetSymbolAddress((void**)&benc, g_benc);
    cudaGetSymbolAddress((void**)&wte,  g_WTe);
    cudaGetSymbolAddress((void**)&wtd,  g_WTd);

    cudaFuncSetAttribute(persist_kernel, cudaFuncAttributeMaxDynamicSharedMemorySize, PERSIST_SMEM);
    cudaFuncSetAttribute(gxmma_kernel, cudaFuncAttributeMaxDynamicSharedMemorySize, GX_SMEM);
    cudaFuncSetAttribute(outmma_kernel, cudaFuncAttributeMaxDynamicSharedMemorySize, OUT_SMEM);

    stats_kernel<<<(BATCH * CIN + 255) / 256, 256>>>(x);
    bias_kernel<<<(G4 + 255) / 256, 256>>>(bih, bhh, Wih, bp);
    wd_kernel<<<dim3(DM / 64, G4 / 64), 256>>>(Wih, Wp, Whh);
    xsplit_kernel<<<(BATCH * TSEQ * CIN + 255) / 256, 256>>>(x);
    wihsplit_kernel<<<dim3(6, 32), 256>>>(Wih);
    wpsplit_kernel<<<dim3(8, 6), 256>>>(Wp);
    wsplit_kernel<<<dim3(8, 32), 256>>>(Whh, wte);
    wsplit_kernel<<<dim3(8, 32), 256>>>(wd, wtd);
    init_kernel<<<((int)(sizeof(g_Hbf) / 4) + 255) / 256, 256>>>();
    gxmma_kernel<<<dim3(32, 192), 256, GX_SMEM>>>();

    persist_kernel<<<dim3(32, 4), 256, PERSIST_SMEM>>>(gx, benc, bd);

    outmma_kernel<<<dim3(6, 192), 256, OUT_SMEM>>>(bp, out);
    (void)in_sizes; (void)n_in; (void)out_size;
}

// round 11
// speedup vs baseline: 2.0071x; 1.0814x over previous
#include <cuda_runtime.h>
#include <cuda_bf16.h>
#include <math.h>
#include <stdint.h>

#define BATCH 256
#define TSEQ  96
#define PRED  96
#define CIN   321
#define DM    512
#define G4    2048
#define HD    (BATCH*DM)
#define NSTEP (TSEQ+PRED-1)     // 191

#define AIMG  36864u            // bf16 image: 256 rows x 144 B per (chunk,split)
#define WIMG  9216u             // bf16 W image: 64 rows x 144 B
#define XIMG  (24576u*144u)

// ---------------- device scratch ----------------------------------------------
__device__ float g_mean[BATCH*CIN];
__device__ float g_std [BATCH*CIN];
__device__ float g_istd[BATCH*CIN];
__device__ float g_Gx  [(size_t)BATCH*TSEQ*G4];
__device__ float g_Wd  [G4*DM];
__device__ float g_bd  [G4];
__device__ float g_benc[G4];
__device__ unsigned g_bar2[NSTEP*4*32];           // per (step,mq) counter, 128B padded
// bf16 hidden images: [par2][chunk8][split2][256][72]
__device__ __align__(1024) unsigned char g_Hbf[2*8*2*AIMG];
// decoder hidden bf16 split images: [d96][chunk8][split2][256][72]
__device__ __align__(1024) unsigned char g_Dbf[(size_t)96*8*2*AIMG];
// recurrent W images: [ntile32][chunk8][split2][64][72]
__device__ __align__(1024) unsigned char g_WTe[32*8*2*WIMG];
__device__ __align__(1024) unsigned char g_WTd[32*8*2*WIMG];
// gx operand images
__device__ __align__(1024) unsigned char g_Xbf[6*2*XIMG];
__device__ __align__(1024) unsigned char g_WIe[32*6*2*WIMG];
// Wp images for out: [ntile6][chunk8][split2][64][72]
__device__ __align__(1024) unsigned char g_WPe[6*8*2*WIMG];

// ---------------- helpers ------------------------------------------------------
__device__ __forceinline__ float sigf(float x) { return 1.f / (1.f + expf(-x)); }
// branchless fast gates for the persistent kernel (error ~1e-6, MUFU-only)
__device__ __forceinline__ float fsig(float x) {
    return __fdividef(1.f, 1.f + __expf(-x));
}
__device__ __forceinline__ float ftanh(float x) {
    return __fdividef(2.f, 1.f + __expf(-2.f * x)) - 1.f;
}

__device__ __forceinline__ uint32_t smem_u32(const void* p) {
    uint32_t a;
    asm("{ .reg .u64 t; cvta.to.shared.u64 t, %1; cvt.u32.u64 %0, t; }" : "=r"(a) : "l"(p));
    return a;
}
__device__ __forceinline__ void cpasync16(uint32_t dst, const void* src) {
    asm volatile("cp.async.cg.shared.global [%0], [%1], 16;" :: "r"(dst), "l"(src) : "memory");
}
#define CP_COMMIT() asm volatile("cp.async.commit_group;" ::: "memory")
#define CP_WAIT(N)  asm volatile("cp.async.wait_group %0;" :: "n"(N) : "memory")

__device__ __forceinline__ void ldsm4(uint32_t* r, uint32_t addr) {
    asm volatile("ldmatrix.sync.aligned.m8n8.x4.shared.b16 {%0,%1,%2,%3}, [%4];"
        : "=r"(r[0]), "=r"(r[1]), "=r"(r[2]), "=r"(r[3]) : "r"(addr));
}
__device__ __forceinline__ void mma16816(float* d, const uint32_t* a, const uint32_t* b) {
    asm volatile("mma.sync.aligned.m16n8k16.row.col.f32.bf16.bf16.f32 "
        "{%0,%1,%2,%3}, {%4,%5,%6,%7}, {%8,%9}, {%0,%1,%2,%3};"
        : "+f"(d[0]), "+f"(d[1]), "+f"(d[2]), "+f"(d[3])
        : "r"(a[0]), "r"(a[1]), "r"(a[2]), "r"(a[3]), "r"(b[0]), "r"(b[1]));
}
__device__ __forceinline__ void bfsplit2(float a, float b, uint32_t& hw, uint32_t& lw) {
    __nv_bfloat16 h0 = __float2bfloat16(a), h1 = __float2bfloat16(b);
    float r0 = a - __bfloat162float(h0), r1 = b - __bfloat162float(h1);
    __nv_bfloat16 l0 = __float2bfloat16(r0), l1 = __float2bfloat16(r1);
    hw = (uint32_t)__bfloat16_as_ushort(h0) | ((uint32_t)__bfloat16_as_ushort(h1) << 16);
    lw = (uint32_t)__bfloat16_as_ushort(l0) | ((uint32_t)__bfloat16_as_ushort(l1) << 16);
}

// ---------------- stats --------------------------------------------------------
__global__ __launch_bounds__(256) void stats_kernel(const float* __restrict__ x) {
    int idx = blockIdx.x * 256 + threadIdx.x;
    if (idx >= BATCH * CIN) return;
    int b = idx / CIN, ch = idx % CIN;
    float s = 0.f, ss = 0.f;
    const float* p = x + (size_t)b * TSEQ * CIN + ch;
    #pragma unroll 4
    for (int t = 0; t < TSEQ; t++) { float v = p[t * CIN]; s += v; ss += v * v; }
    float mean = s * (1.f / TSEQ);
    float var = ss * (1.f / TSEQ) - mean * mean;
    if (var < 0.f) var = 0.f;
    float sd = sqrtf(var + 1e-5f);
    g_mean[idx] = mean; g_std[idx] = sd; g_istd[idx] = 1.f / sd;
}

// ---------------- bias fold ----------------------------------------------------
__global__ __launch_bounds__(256) void bias_kernel(const float* __restrict__ bih,
                                                   const float* __restrict__ bhh,
                                                   const float* __restrict__ Wih,
                                                   const float* __restrict__ bp) {
    int n = blockIdx.x * 256 + threadIdx.x;
    if (n >= G4) return;
    float be = bih[n] + bhh[n];
    float s = 0.f;
    const float* w = Wih + (size_t)n * CIN;
    for (int j = 0; j < CIN; j++) s += w[j] * bp[j];
    g_benc[n] = be;
    g_bd[n] = be + s;
}

// ---------------- Wd = Whh + Wih @ Wp ------------------------------------------
__global__ __launch_bounds__(256) void wd_kernel(const float* __restrict__ Wih,
                                                 const float* __restrict__ Wp,
                                                 const float* __restrict__ Whh) {
    __shared__ float As[64 * 17];
    __shared__ float Bs[16 * 65];
    int tid = threadIdx.x;
    int n0 = blockIdx.x * 64;
    int m0 = blockIdx.y * 64;
    int tr = tid >> 4, tc = tid & 15;
    float acc[4][4] = {};
    for (int j0 = 0; j0 < CIN; j0 += 16) {
        #pragma unroll
        for (int i = 0; i < 4; i++) {
            int l = tid + 256 * i;
            int mr = l >> 4, jj = l & 15;
            int j = j0 + jj;
            As[mr * 17 + jj] = (j < CIN) ? Wih[(size_t)(m0 + mr) * CIN + j] : 0.f;
        }
        #pragma unroll
        for (int i = 0; i < 4; i++) {
            int l = tid + 256 * i;
            int jj = l >> 6, nr = l & 63;
            int j = j0 + jj;
            Bs[jj * 65 + nr] = (j < CIN) ? Wp[(size_t)j * DM + n0 + nr] : 0.f;
        }
        __syncthreads();
        #pragma unroll
        for (int jj = 0; jj < 16; jj++) {
            float a[4], bb[4];
            #pragma unroll
            for (int r = 0; r < 4; r++) a[r] = As[(tr * 4 + r) * 17 + jj];
            #pragma unroll
            for (int cc = 0; cc < 4; cc++) bb[cc] = Bs[jj * 65 + tc * 4 + cc];
            #pragma unroll
            for (int r = 0; r < 4; r++)
                #pragma unroll
                for (int cc = 0; cc < 4; cc++) acc[r][cc] += a[r] * bb[cc];
        }
        __syncthreads();
    }
    #pragma unroll
    for (int r = 0; r < 4; r++) {
        int m = m0 + tr * 4 + r;
        #pragma unroll
        for (int cc = 0; cc < 4; cc++) {
            int n = n0 + tc * 4 + cc;
            g_Wd[(size_t)m * DM + n] = Whh[(size_t)m * DM + n] + acc[r][cc];
        }
    }
}

// ---------------- recurrent W image builder ------------------------------------
__global__ __launch_bounds__(256) void wsplit_kernel(const float* __restrict__ src,
                                                     unsigned char* __restrict__ dst) {
    int chunk = blockIdx.x;
    int ntile = blockIdx.y;
    int tid = threadIdx.x;
    int rr = tid >> 2;
    int q  = tid & 3;
    int joct = rr >> 5, rem = rr & 31;
    int gate = rem >> 3, j7 = rem & 7;
    int srow = gate * DM + ntile * 16 + joct * 8 + j7;
    unsigned char* d0 = dst + ((size_t)(ntile * 8 + chunk) * 2) * WIMG;
    #pragma unroll
    for (int c = 0; c < 18; c++) {
        int col = q * 18 + c;
        float v = (col < 64) ? src[(size_t)srow * DM + chunk * 64 + col] : 0.f;
        __nv_bfloat16 hb = __float2bfloat16(v);
        float rem2 = v - __bfloat162float(hb);
        __nv_bfloat16 lb = __float2bfloat16(rem2);
        size_t off = (size_t)rr * 144 + col * 2;
        *(__nv_bfloat16*)(d0 + off)        = hb;
        *(__nv_bfloat16*)(d0 + WIMG + off) = lb;
    }
}

// ---------------- Wih image builder for gx -------------------------------------
__global__ __launch_bounds__(256) void wihsplit_kernel(const float* __restrict__ Wih) {
    int chunk = blockIdx.x;
    int ntile = blockIdx.y;
    int tid = threadIdx.x;
    int rr = tid >> 2;
    int q  = tid & 3;
    int srow = ntile * 64 + rr;
    unsigned char* d0 = g_WIe + ((size_t)(ntile * 6 + chunk) * 2) * WIMG;
    #pragma unroll
    for (int c = 0; c < 18; c++) {
        int col = q * 18 + c;
        int k = chunk * 64 + col;
        float v = (col < 64 && k < CIN) ? Wih[(size_t)srow * CIN + k] : 0.f;
        __nv_bfloat16 hb = __float2bfloat16(v);
        float rem2 = v - __bfloat162float(hb);
        __nv_bfloat16 lb = __float2bfloat16(rem2);
        size_t off = (size_t)rr * 144 + col * 2;
        *(__nv_bfloat16*)(d0 + off)        = hb;
        *(__nv_bfloat16*)(d0 + WIMG + off) = lb;
    }
}

// ---------------- Wp image builder for out -------------------------------------
__global__ __launch_bounds__(256) void wpsplit_kernel(const float* __restrict__ Wp) {
    int chunk = blockIdx.x;   // 0..7
    int ntile = blockIdx.y;   // 0..5
    int tid = threadIdx.x;
    int rr = tid >> 2;
    int q  = tid & 3;
    int n = ntile * 64 + rr;
    unsigned char* d0 = g_WPe + ((size_t)(ntile * 8 + chunk) * 2) * WIMG;
    #pragma unroll
    for (int c = 0; c < 18; c++) {
        int col = q * 18 + c;
        int k = chunk * 64 + col;
        float v = (col < 64 && n < CIN) ? Wp[(size_t)n * DM + k] : 0.f;
        __nv_bfloat16 hb = __float2bfloat16(v);
        float rem2 = v - __bfloat162float(hb);
        __nv_bfloat16 lb = __float2bfloat16(rem2);
        size_t off = (size_t)rr * 144 + col * 2;
        *(__nv_bfloat16*)(d0 + off)        = hb;
        *(__nv_bfloat16*)(d0 + WIMG + off) = lb;
    }
}

// ---------------- x normalize+split images -------------------------------------
__global__ __launch_bounds__(256) void xsplit_kernel(const float* __restrict__ x) {
    int idx = blockIdx.x * 256 + threadIdx.x;
    if (idx >= BATCH * TSEQ * CIN) return;
    int m = idx / CIN, k = idx - m * CIN;
    int b = m / TSEQ;
    int bc = b * CIN + k;
    float v = (x[idx] - g_mean[bc]) * g_istd[bc];
    __nv_bfloat16 hb = __float2bfloat16(v);
    float rem = v - __bfloat162float(hb);
    __nv_bfloat16 lb = __float2bfloat16(rem);
    int chunk = k >> 6, col = k & 63;
    size_t offh = ((size_t)(chunk * 2) * 24576 + m) * 144 + col * 2;
    *(__nv_bfloat16*)(g_Xbf + offh)        = hb;
    *(__nv_bfloat16*)(g_Xbf + offh + XIMG) = lb;
}

// ---------------- init ----------------------------------------------------------
__global__ __launch_bounds__(256) void init_kernel() {
    int i = blockIdx.x * 256 + threadIdx.x;
    if (i < (int)(sizeof(g_Hbf) / 4)) ((uint32_t*)g_Hbf)[i] = 0u;
    if (i < NSTEP * 4 * 32) g_bar2[i] = 0u;
}

// ---------------- gx = xnorm @ Wih^T via HMMA split ----------------------------
#define GXSTAGE 55296
#define GX_SMEM (2*GXSTAGE)
__global__ void __launch_bounds__(256, 1) gxmma_kernel() {
    extern __shared__ unsigned char smem[];
    const int tid = threadIdx.x;
    const int w = tid >> 5, lane = tid & 31;
    const int n0 = blockIdx.x * 64;
    const int m0 = blockIdx.y * 128;
    uint32_t sbase = smem_u32(smem);
    float acc[8][4];
    #pragma unroll
    for (int f = 0; f < 8; f++)
        #pragma unroll
        for (int r = 0; r < 4; r++) acc[f][r] = 0.f;

    const uint32_t aoff = (uint32_t)((w * 16 + (lane & 15)) * 144 + (lane >> 4) * 16);
    const uint32_t boff = (uint32_t)(((((lane >> 4) & 1) * 8) + (lane & 7)) * 144 + ((lane >> 3) & 1) * 16);
    const unsigned char* Bbase = g_WIe + ((size_t)blockIdx.x * 6 * 2) * WIMG;

    auto issue = [&](int chunk, int buf) {
        uint32_t sb = sbase + buf * GXSTAGE;
        #pragma unroll
        for (int i = 0; i < 14; i++) {
            int idx = tid + i * 256;
            if (idx >= 3456) break;
            uint32_t dst; const unsigned char* src;
            if (idx < 2304) {
                int sp = idx / 1152; int off = (idx - sp * 1152) * 16;
                dst = sb + sp * 18432 + off;
                src = g_Xbf + (size_t)(chunk * 2 + sp) * XIMG + (size_t)m0 * 144 + off;
            } else {
                int j = idx - 2304; int sp = j / 576; int off = (j - sp * 576) * 16;
                dst = sb + 36864 + sp * 9216 + off;
                src = Bbase + (size_t)(chunk * 2 + sp) * WIMG + off;
            }
            cpasync16(dst, src);
        }
        CP_COMMIT();
    };

    issue(0, 0); issue(1, 1);
    #pragma unroll 1
    for (int c = 0; c < 6; c++) {
        if (c < 5) { CP_WAIT(1); } else { CP_WAIT(0); }
        __syncthreads();
        uint32_t st = sbase + (c & 1) * GXSTAGE;
        uint32_t sAhi = st, sAlo = st + 18432, sWhi = st + 36864, sWlo = st + 46080;
        #pragma unroll
        for (int kf = 0; kf < 4; kf++) {
            uint32_t ah[4], al[4], bh[4][4], bl[4][4];
            ldsm4(ah, sAhi + aoff + kf * 32);
            ldsm4(al, sAlo + aoff + kf * 32);
            #pragma unroll
            for (int ng = 0; ng < 4; ng++) {
                ldsm4(bh[ng], sWhi + boff + ng * 2304 + kf * 32);
                ldsm4(bl[ng], sWlo + boff + ng * 2304 + kf * 32);
            }
            #pragma unroll
            for (int ng = 0; ng < 4; ng++) { mma16816(acc[2*ng], ah, bh[ng]); mma16816(acc[2*ng+1], ah, bh[ng]+2); }
            #pragma unroll
            for (int ng = 0; ng < 4; ng++) { mma16816(acc[2*ng], ah, bl[ng]); mma16816(acc[2*ng+1], ah, bl[ng]+2); }
            #pragma unroll
            for (int ng = 0; ng < 4; ng++) { mma16816(acc[2*ng], al, bh[ng]); mma16816(acc[2*ng+1], al, bh[ng]+2); }
        }
        __syncthreads();
        if (c + 2 < 6) issue(c + 2, c & 1);
    }
    #pragma unroll
    for (int f = 0; f < 8; f++) {
        int n = n0 + (f >> 1) * 16 + (f & 1) * 8 + (lane & 3) * 2;
        #pragma unroll
        for (int rowi = 0; rowi < 2; rowi++) {
            int m = m0 + w * 16 + (lane >> 2) + rowi * 8;
            *(float2*)&g_Gx[(size_t)m * G4 + n] = make_float2(acc[f][rowi*2], acc[f][rowi*2+1]);
        }
    }
}

// ---------------- persistent LSTM kernel (bf16 3-term, per-mq barrier) ---------
#define WCACHE_B 147456
#define ABUF_B   18432
#define PERSIST_SMEM (WCACHE_B + 3*ABUF_B)

__global__ void __launch_bounds__(256, 1) persist_kernel(const float* __restrict__ gx,
                                                         const float* __restrict__ benc,
                                                         const float* __restrict__ bd) {
    extern __shared__ unsigned char smem[];
    const int tid = threadIdx.x;
    const int w = tid >> 5, lane = tid & 31;
    const int wr = w & 3, wc = w >> 2;
    const int ntile = blockIdx.x, mq = blockIdx.y;
    uint32_t sbase = smem_u32(smem);
    uint32_t Wc = sbase;
    uint32_t Ab = sbase + WCACHE_B;

    const uint32_t aoff = (uint32_t)((wr * 16 + (lane & 15)) * 144 + (lane >> 4) * 16);
    const uint32_t boff = (uint32_t)((wc * 32 + ((lane >> 4) & 1) * 8 + (lane & 7)) * 144 + ((lane >> 3) & 1) * 16);

    const unsigned char* WEsrc = g_WTe + ((size_t)(ntile * 8) * 2) * WIMG;
    const unsigned char* WDsrc = g_WTd + ((size_t)(ntile * 8) * 2) * WIMG;

    auto loadW = [&](const unsigned char* src) {
        #pragma unroll 4
        for (int i = 0; i < 36; i++) {
            int idx = tid + i * 256;
            int img = idx / 576;
            int off = (idx - img * 576) * 16;
            cpasync16(Wc + img * 9216 + off, src + (size_t)img * WIMG + off);
        }
        CP_COMMIT();
    };
    auto loadA = [&](const unsigned char* Apar, int chunk, int buf) {
        #pragma unroll
        for (int i = 0; i < 5; i++) {
            int idx = tid + i * 256;
            if (idx < 1152) {
                int split = idx / 576;
                int off = (idx - split * 576) * 16;
                cpasync16(Ab + buf * ABUF_B + split * 9216 + off,
                          Apar + (size_t)(chunk * 2 + split) * AIMG + mq * 9216 + off);
            }
        }
        CP_COMMIT();
    };

    const int j0 = ntile * 16 + wc * 8 + (lane & 3) * 2;
    const int bbase = mq * 64 + wr * 16 + (lane >> 2);
    const int chunkA = ntile >> 2;
    const size_t colOff = (size_t)((ntile & 3) * 16 + wc * 8 + (lane & 3) * 2) * 2;

    float bi[4][2];
    #pragma unroll
    for (int g = 0; g < 4; g++) { bi[g][0] = benc[g * DM + j0]; bi[g][1] = benc[g * DM + j0 + 1]; }
    float creg[4] = {0.f, 0.f, 0.f, 0.f};

    loadW(WEsrc);
    CP_WAIT(0);
    __syncthreads();

    for (int s = 0; s < NSTEP; s++) {
        const bool enc = (s < TSEQ);
        if (s == TSEQ) {
            __syncthreads();
            loadW(WDsrc);
            #pragma unroll
            for (int g = 0; g < 4; g++) { bi[g][0] = bd[g * DM + j0]; bi[g][1] = bd[g * DM + j0 + 1]; }
            CP_WAIT(0);
            __syncthreads();
        }
        const int par = s & 1;
        const unsigned char* Apar = g_Hbf + (size_t)(par * 16) * AIMG;

        float pr[16];
        if (enc) {
            #pragma unroll
            for (int rowi = 0; rowi < 2; rowi++) {
                const float* gr = gx + ((size_t)(bbase + rowi * 8) * TSEQ + s) * G4;
                #pragma unroll
                for (int g = 0; g < 4; g++) {
                    float2 v = *(const float2*)&gr[g * DM + j0];
                    pr[rowi * 8 + g * 2]     = v.x;
                    pr[rowi * 8 + g * 2 + 1] = v.y;
                }
            }
        }

        float acc[4][4];
        #pragma unroll
        for (int g = 0; g < 4; g++)
            #pragma unroll
            for (int r = 0; r < 4; r++) acc[g][r] = 0.f;

        if (s > 0) {    // s==0: h=0, MMA result is all zeros — skip loads+MMA entirely
            loadA(Apar, 0, 0);
            loadA(Apar, 1, 1);
            #pragma unroll 1
            for (int c = 0; c < 8; c++) {
                if (c + 2 < 8) { loadA(Apar, c + 2, (c + 2) % 3); CP_WAIT(2); }
                else if (c == 6) { CP_WAIT(1); }
                else if (c == 7) { CP_WAIT(0); }
                __syncthreads();
                uint32_t at = Ab + (c % 3) * ABUF_B;
                uint32_t sAhi = at, sAlo = at + 9216;
                uint32_t wt = Wc + c * 18432;
                uint32_t sWhi = wt, sWlo = wt + 9216;
                #pragma unroll
                for (int kf = 0; kf < 4; kf++) {
                    uint32_t ah[4], al[4], bh0[4], bh1[4], bl0[4], bl1[4];
                    ldsm4(ah,  sAhi + aoff + kf * 32);
                    ldsm4(al,  sAlo + aoff + kf * 32);
                    ldsm4(bh0, sWhi + boff + kf * 32);
                    ldsm4(bh1, sWhi + boff + 2304 + kf * 32);
                    ldsm4(bl0, sWlo + boff + kf * 32);
                    ldsm4(bl1, sWlo + boff + 2304 + kf * 32);
                    mma16816(acc[0], ah, bh0); mma16816(acc[1], ah, bh0 + 2);
                    mma16816(acc[2], ah, bh1); mma16816(acc[3], ah, bh1 + 2);
                    mma16816(acc[0], ah, bl0); mma16816(acc[1], ah, bl0 + 2);
                    mma16816(acc[2], ah, bl1); mma16816(acc[3], ah, bl1 + 2);
                    mma16816(acc[0], al, bh0); mma16816(acc[1], al, bh0 + 2);
                    mma16816(acc[2], al, bh1); mma16816(acc[3], al, bh1 + 2);
                }
                __syncthreads();
            }
        }

        // ---- epilogue ----
        unsigned char* imgHi = g_Hbf + (size_t)(((par ^ 1) * 8 + chunkA) * 2) * AIMG;
        unsigned char* imgLo = imgHi + AIMG;
        unsigned char* decHi = nullptr;
        if (s >= TSEQ - 1) {
            int d = s - (TSEQ - 1);
            decHi = g_Dbf + (size_t)((d * 8 + chunkA) * 2) * AIMG;
        }

        #pragma unroll
        for (int rowi = 0; rowi < 2; rowi++) {
            int b = bbase + rowi * 8;
            float h2[2];
            #pragma unroll
            for (int cp = 0; cp < 2; cp++) {
                float gi = acc[0][rowi * 2 + cp] + bi[0][cp];
                float gf = acc[1][rowi * 2 + cp] + bi[1][cp];
                float gg = acc[2][rowi * 2 + cp] + bi[2][cp];
                float go = acc[3][rowi * 2 + cp] + bi[3][cp];
                if (enc) {
                    gi += pr[rowi * 8 + 0 + cp];
                    gf += pr[rowi * 8 + 2 + cp];
                    gg += pr[rowi * 8 + 4 + cp];
                    go += pr[rowi * 8 + 6 + cp];
                }
                float cn = fsig(gf) * creg[rowi * 2 + cp] + fsig(gi) * ftanh(gg);
                float hn = fsig(go) * ftanh(cn);
                creg[rowi * 2 + cp] = cn;
                h2[cp] = hn;
            }
            uint32_t hw, lw;
            bfsplit2(h2[0], h2[1], hw, lw);
            size_t off = (size_t)b * 144 + colOff;
            *(uint32_t*)(imgHi + off) = hw;
            *(uint32_t*)(imgLo + off) = lw;
            if (decHi) {
                *(uint32_t*)(decHi + off) = hw;
                *(uint32_t*)(decHi + AIMG + off) = lw;
            }
        }

        // ---- per-mq grid barrier (32 blocks, padded counter) ----
        if (s < NSTEP - 1) {
            __threadfence();
            __syncthreads();
            if (tid == 0) {
                unsigned* p = &g_bar2[(s * 4 + mq) * 32];
                unsigned prev = atomicAdd(p, 1u);
                if (prev != 31u) {
                    unsigned v;
                    do {
                        asm volatile("ld.acquire.gpu.u32 %0, [%1];" : "=r"(v) : "l"(p) : "memory");
                    } while (v < 32u);
                }
            }
            __syncthreads();
        }
    }
}

// ---------------- out: Y = Dbf @ Wp^T via HMMA, denormalize, scatter -----------
#define OSTAGE 55296
#define OUT_SMEM (2*OSTAGE)
__global__ void __launch_bounds__(256, 1) outmma_kernel(const float* __restrict__ bp,
                                                        float* __restrict__ out) {
    extern __shared__ unsigned char smem[];
    const int tid = threadIdx.x;
    const int w = tid >> 5, lane = tid & 31;
    const int ntile = blockIdx.x;        // 0..5
    const int mt = blockIdx.y;           // 0..191
    const int d = mt >> 1, half = mt & 1;
    const int m0 = half * 128;
    uint32_t sbase = smem_u32(smem);
    float acc[8][4];
    #pragma unroll
    for (int f = 0; f < 8; f++)
        #pragma unroll
        for (int r = 0; r < 4; r++) acc[f][r] = 0.f;

    const uint32_t aoff = (uint32_t)((w * 16 + (lane & 15)) * 144 + (lane >> 4) * 16);
    const uint32_t boff = (uint32_t)(((((lane >> 4) & 1) * 8) + (lane & 7)) * 144 + ((lane >> 3) & 1) * 16);
    const unsigned char* Abase = g_Dbf + (size_t)(d * 16) * AIMG;
    const unsigned char* Bbase = g_WPe + ((size_t)(ntile * 8) * 2) * WIMG;

    auto issue = [&](int chunk, int buf) {
        uint32_t sb = sbase + buf * OSTAGE;
        #pragma unroll
        for (int i = 0; i < 14; i++) {
            int idx = tid + i * 256;
            if (idx >= 3456) break;
            uint32_t dst; const unsigned char* src;
            if (idx < 2304) {
                int sp = idx / 1152; int off = (idx - sp * 1152) * 16;
                dst = sb + sp * 18432 + off;
                src = Abase + (size_t)(chunk * 2 + sp) * AIMG + (size_t)m0 * 144 + off;
            } else {
                int j = idx - 2304; int sp = j / 576; int off = (j - sp * 576) * 16;
                dst = sb + 36864 + sp * 9216 + off;
                src = Bbase + (size_t)(chunk * 2 + sp) * WIMG + off;
            }
            cpasync16(dst, src);
        }
        CP_COMMIT();
    };

    issue(0, 0); issue(1, 1);
    #pragma unroll 1
    for (int c = 0; c < 8; c++) {
        if (c < 7) { CP_WAIT(1); } else { CP_WAIT(0); }
        __syncthreads();
        uint32_t st = sbase + (c & 1) * OSTAGE;
        uint32_t sAhi = st, sAlo = st + 18432, sWhi = st + 36864, sWlo = st + 46080;
        #pragma unroll
        for (int kf = 0; kf < 4; kf++) {
            uint32_t ah[4], al[4], bh[4][4], bl[4][4];
            ldsm4(ah, sAhi + aoff + kf * 32);
            ldsm4(al, sAlo + aoff + kf * 32);
            #pragma unroll
            for (int ng = 0; ng < 4; ng++) {
                ldsm4(bh[ng], sWhi + boff + ng * 2304 + kf * 32);
                ldsm4(bl[ng], sWlo + boff + ng * 2304 + kf * 32);
            }
            #pragma unroll
            for (int ng = 0; ng < 4; ng++) { mma16816(acc[2*ng], ah, bh[ng]); mma16816(acc[2*ng+1], ah, bh[ng]+2); }
            #pragma unroll
            for (int ng = 0; ng < 4; ng++) { mma16816(acc[2*ng], ah, bl[ng]); mma16816(acc[2*ng+1], ah, bl[ng]+2); }
            #pragma unroll
            for (int ng = 0; ng < 4; ng++) { mma16816(acc[2*ng], al, bh[ng]); mma16816(acc[2*ng+1], al, bh[ng]+2); }
        }
        __syncthreads();
        if (c + 2 < 8) issue(c + 2, c & 1);
    }
    #pragma unroll
    for (int f = 0; f < 8; f++) {
        int gn = ntile * 64 + (f >> 1) * 16 + (f & 1) * 8 + (lane & 3) * 2;
        #pragma unroll
        for (int rowi = 0; rowi < 2; rowi++) {
            int b = m0 + w * 16 + (lane >> 2) + rowi * 8;
            #pragma unroll
            for (int cp = 0; cp < 2; cp++) {
                int n = gn + cp;
                if (n < CIN) {
                    int bc = b * CIN + n;
                    float y = acc[f][rowi * 2 + cp] + bp[n];
                    out[(size_t)b * PRED * CIN + (size_t)d * CIN + n] =
                        y * g_std[bc] + g_mean[bc];
                }
            }
        }
    }
}

// ---------------- host launcher ------------------------------------------------
extern "C" void kernel_launch(void* const* d_in, const int* in_sizes, int n_in,
                              void* d_out, int out_size) {
    const float* x   = (const float*)d_in[0];
    const float* Wih = (const float*)d_in[1];
    const float* Whh = (const float*)d_in[2];
    const float* bih = (const float*)d_in[3];
    const float* bhh = (const float*)d_in[4];
    const float* Wp  = (const float*)d_in[5];
    const float* bp  = (const float*)d_in[6];
    float* out = (float*)d_out;

    float *gx, *wd, *bd, *benc;
    unsigned char *wte, *wtd;
    cudaGetSymbolAddress((void**)&gx,   g_Gx);
    cudaGetSymbolAddress((void**)&wd,   g_Wd);
    cudaGetSymbolAddress((void**)&bd,   g_bd);
    cudaGetSymbolAddress((void**)&benc, g_benc);
    cudaGetSymbolAddress((void**)&wte,  g_WTe);
    cudaGetSymbolAddress((void**)&wtd,  g_WTd);

    cudaFuncSetAttribute(persist_kernel, cudaFuncAttributeMaxDynamicSharedMemorySize, PERSIST_SMEM);
    cudaFuncSetAttribute(gxmma_kernel, cudaFuncAttributeMaxDynamicSharedMemorySize, GX_SMEM);
    cudaFuncSetAttribute(outmma_kernel, cudaFuncAttributeMaxDynamicSharedMemorySize, OUT_SMEM);

    stats_kernel<<<(BATCH * CIN + 255) / 256, 256>>>(x);
    bias_kernel<<<(G4 + 255) / 256, 256>>>(bih, bhh, Wih, bp);
    wd_kernel<<<dim3(DM / 64, G4 / 64), 256>>>(Wih, Wp, Whh);
    xsplit_kernel<<<(BATCH * TSEQ * CIN + 255) / 256, 256>>>(x);
    wihsplit_kernel<<<dim3(6, 32), 256>>>(Wih);
    wpsplit_kernel<<<dim3(8, 6), 256>>>(Wp);
    wsplit_kernel<<<dim3(8, 32), 256>>>(Whh, wte);
    wsplit_kernel<<<dim3(8, 32), 256>>>(wd, wtd);
    init_kernel<<<((int)(sizeof(g_Hbf) / 4) + 255) / 256, 256>>>();
    gxmma_kernel<<<dim3(32, 192), 256, GX_SMEM>>>();

    persist_kernel<<<dim3(32, 4), 256, PERSIST_SMEM>>>(gx, benc, bd);

    outmma_kernel<<<dim3(6, 192), 256, OUT_SMEM>>>(bp, out);
    (void)in_sizes; (void)n_in; (void)out_size;
}

// round 12
// speedup vs baseline: 2.0128x; 1.0028x over previous
#include <cuda_runtime.h>
#include <cuda_bf16.h>
#include <math.h>
#include <stdint.h>

#define BATCH 256
#define TSEQ  96
#define PRED  96
#define CIN   321
#define DM    512
#define G4    2048
#define HD    (BATCH*DM)
#define NSTEP (TSEQ+PRED-1)     // 191

#define AIMG  36864u            // bf16 image: 256 rows x 144 B per (chunk,split)
#define WIMG  9216u             // bf16 W image: 64 rows x 144 B
#define XIMG  (24576u*144u)

// ---------------- device scratch ----------------------------------------------
__device__ float g_mean[BATCH*CIN];
__device__ float g_std [BATCH*CIN];
__device__ float g_istd[BATCH*CIN];
__device__ float g_Gx  [(size_t)BATCH*TSEQ*G4];
__device__ float g_Wd  [G4*DM];
__device__ float g_bd  [G4];
__device__ float g_benc[G4];
__device__ unsigned g_bar2[NSTEP*4*32];           // per (step,mq) counter, 128B padded
// bf16 hidden images: [par2][chunk8][split2][256][72]
__device__ __align__(1024) unsigned char g_Hbf[2*8*2*AIMG];
// decoder hidden bf16 split images: [d96][chunk8][split2][256][72]
__device__ __align__(1024) unsigned char g_Dbf[(size_t)96*8*2*AIMG];
// recurrent W images: [ntile32][chunk8][split2][64][72]
__device__ __align__(1024) unsigned char g_WTe[32*8*2*WIMG];
__device__ __align__(1024) unsigned char g_WTd[32*8*2*WIMG];
// gx operand images
__device__ __align__(1024) unsigned char g_Xbf[6*2*XIMG];
__device__ __align__(1024) unsigned char g_WIe[32*6*2*WIMG];
// Wp images for out: [ntile6][chunk8][split2][64][72]
__device__ __align__(1024) unsigned char g_WPe[6*8*2*WIMG];

// ---------------- helpers ------------------------------------------------------
__device__ __forceinline__ float sigf(float x) { return 1.f / (1.f + expf(-x)); }
// branchless fast gates for the persistent kernel (error ~1e-6, MUFU-only)
__device__ __forceinline__ float fsig(float x) {
    return __fdividef(1.f, 1.f + __expf(-x));
}
__device__ __forceinline__ float ftanh(float x) {
    return __fdividef(2.f, 1.f + __expf(-2.f * x)) - 1.f;
}

__device__ __forceinline__ uint32_t smem_u32(const void* p) {
    uint32_t a;
    asm("{ .reg .u64 t; cvta.to.shared.u64 t, %1; cvt.u32.u64 %0, t; }" : "=r"(a) : "l"(p));
    return a;
}
__device__ __forceinline__ void cpasync16(uint32_t dst, const void* src) {
    asm volatile("cp.async.cg.shared.global [%0], [%1], 16;" :: "r"(dst), "l"(src) : "memory");
}
#define CP_COMMIT() asm volatile("cp.async.commit_group;" ::: "memory")
#define CP_WAIT(N)  asm volatile("cp.async.wait_group %0;" :: "n"(N) : "memory")

__device__ __forceinline__ void ldsm4(uint32_t* r, uint32_t addr) {
    asm volatile("ldmatrix.sync.aligned.m8n8.x4.shared.b16 {%0,%1,%2,%3}, [%4];"
        : "=r"(r[0]), "=r"(r[1]), "=r"(r[2]), "=r"(r[3]) : "r"(addr));
}
__device__ __forceinline__ void mma16816(float* d, const uint32_t* a, const uint32_t* b) {
    asm volatile("mma.sync.aligned.m16n8k16.row.col.f32.bf16.bf16.f32 "
        "{%0,%1,%2,%3}, {%4,%5,%6,%7}, {%8,%9}, {%0,%1,%2,%3};"
        : "+f"(d[0]), "+f"(d[1]), "+f"(d[2]), "+f"(d[3])
        : "r"(a[0]), "r"(a[1]), "r"(a[2]), "r"(a[3]), "r"(b[0]), "r"(b[1]));
}
__device__ __forceinline__ void bfsplit2(float a, float b, uint32_t& hw, uint32_t& lw) {
    __nv_bfloat16 h0 = __float2bfloat16(a), h1 = __float2bfloat16(b);
    float r0 = a - __bfloat162float(h0), r1 = b - __bfloat162float(h1);
    __nv_bfloat16 l0 = __float2bfloat16(r0), l1 = __float2bfloat16(r1);
    hw = (uint32_t)__bfloat16_as_ushort(h0) | ((uint32_t)__bfloat16_as_ushort(h1) << 16);
    lw = (uint32_t)__bfloat16_as_ushort(l0) | ((uint32_t)__bfloat16_as_ushort(l1) << 16);
}

// ---------------- stats --------------------------------------------------------
__global__ __launch_bounds__(256) void stats_kernel(const float* __restrict__ x) {
    int idx = blockIdx.x * 256 + threadIdx.x;
    if (idx >= BATCH * CIN) return;
    int b = idx / CIN, ch = idx % CIN;
    float s = 0.f, ss = 0.f;
    const float* p = x + (size_t)b * TSEQ * CIN + ch;
    #pragma unroll 4
    for (int t = 0; t < TSEQ; t++) { float v = p[t * CIN]; s += v; ss += v * v; }
    float mean = s * (1.f / TSEQ);
    float var = ss * (1.f / TSEQ) - mean * mean;
    if (var < 0.f) var = 0.f;
    float sd = sqrtf(var + 1e-5f);
    g_mean[idx] = mean; g_std[idx] = sd; g_istd[idx] = 1.f / sd;
}

// ---------------- bias fold ----------------------------------------------------
__global__ __launch_bounds__(256) void bias_kernel(const float* __restrict__ bih,
                                                   const float* __restrict__ bhh,
                                                   const float* __restrict__ Wih,
                                                   const float* __restrict__ bp) {
    int n = blockIdx.x * 256 + threadIdx.x;
    if (n >= G4) return;
    float be = bih[n] + bhh[n];
    float s = 0.f;
    const float* w = Wih + (size_t)n * CIN;
    for (int j = 0; j < CIN; j++) s += w[j] * bp[j];
    g_benc[n] = be;
    g_bd[n] = be + s;
}

// ---------------- Wd = Whh + Wih @ Wp ------------------------------------------
__global__ __launch_bounds__(256) void wd_kernel(const float* __restrict__ Wih,
                                                 const float* __restrict__ Wp,
                                                 const float* __restrict__ Whh) {
    __shared__ float As[64 * 17];
    __shared__ float Bs[16 * 65];
    int tid = threadIdx.x;
    int n0 = blockIdx.x * 64;
    int m0 = blockIdx.y * 64;
    int tr = tid >> 4, tc = tid & 15;
    float acc[4][4] = {};
    for (int j0 = 0; j0 < CIN; j0 += 16) {
        #pragma unroll
        for (int i = 0; i < 4; i++) {
            int l = tid + 256 * i;
            int mr = l >> 4, jj = l & 15;
            int j = j0 + jj;
            As[mr * 17 + jj] = (j < CIN) ? Wih[(size_t)(m0 + mr) * CIN + j] : 0.f;
        }
        #pragma unroll
        for (int i = 0; i < 4; i++) {
            int l = tid + 256 * i;
            int jj = l >> 6, nr = l & 63;
            int j = j0 + jj;
            Bs[jj * 65 + nr] = (j < CIN) ? Wp[(size_t)j * DM + n0 + nr] : 0.f;
        }
        __syncthreads();
        #pragma unroll
        for (int jj = 0; jj < 16; jj++) {
            float a[4], bb[4];
            #pragma unroll
            for (int r = 0; r < 4; r++) a[r] = As[(tr * 4 + r) * 17 + jj];
            #pragma unroll
            for (int cc = 0; cc < 4; cc++) bb[cc] = Bs[jj * 65 + tc * 4 + cc];
            #pragma unroll
            for (int r = 0; r < 4; r++)
                #pragma unroll
                for (int cc = 0; cc < 4; cc++) acc[r][cc] += a[r] * bb[cc];
        }
        __syncthreads();
    }
    #pragma unroll
    for (int r = 0; r < 4; r++) {
        int m = m0 + tr * 4 + r;
        #pragma unroll
        for (int cc = 0; cc < 4; cc++) {
            int n = n0 + tc * 4 + cc;
            g_Wd[(size_t)m * DM + n] = Whh[(size_t)m * DM + n] + acc[r][cc];
        }
    }
}

// ---------------- recurrent W image builder ------------------------------------
__global__ __launch_bounds__(256) void wsplit_kernel(const float* __restrict__ src,
                                                     unsigned char* __restrict__ dst) {
    int chunk = blockIdx.x;
    int ntile = blockIdx.y;
    int tid = threadIdx.x;
    int rr = tid >> 2;
    int q  = tid & 3;
    int joct = rr >> 5, rem = rr & 31;
    int gate = rem >> 3, j7 = rem & 7;
    int srow = gate * DM + ntile * 16 + joct * 8 + j7;
    unsigned char* d0 = dst + ((size_t)(ntile * 8 + chunk) * 2) * WIMG;
    #pragma unroll
    for (int c = 0; c < 18; c++) {
        int col = q * 18 + c;
        float v = (col < 64) ? src[(size_t)srow * DM + chunk * 64 + col] : 0.f;
        __nv_bfloat16 hb = __float2bfloat16(v);
        float rem2 = v - __bfloat162float(hb);
        __nv_bfloat16 lb = __float2bfloat16(rem2);
        size_t off = (size_t)rr * 144 + col * 2;
        *(__nv_bfloat16*)(d0 + off)        = hb;
        *(__nv_bfloat16*)(d0 + WIMG + off) = lb;
    }
}

// ---------------- Wih image builder for gx -------------------------------------
__global__ __launch_bounds__(256) void wihsplit_kernel(const float* __restrict__ Wih) {
    int chunk = blockIdx.x;
    int ntile = blockIdx.y;
    int tid = threadIdx.x;
    int rr = tid >> 2;
    int q  = tid & 3;
    int srow = ntile * 64 + rr;
    unsigned char* d0 = g_WIe + ((size_t)(ntile * 6 + chunk) * 2) * WIMG;
    #pragma unroll
    for (int c = 0; c < 18; c++) {
        int col = q * 18 + c;
        int k = chunk * 64 + col;
        float v = (col < 64 && k < CIN) ? Wih[(size_t)srow * CIN + k] : 0.f;
        __nv_bfloat16 hb = __float2bfloat16(v);
        float rem2 = v - __bfloat162float(hb);
        __nv_bfloat16 lb = __float2bfloat16(rem2);
        size_t off = (size_t)rr * 144 + col * 2;
        *(__nv_bfloat16*)(d0 + off)        = hb;
        *(__nv_bfloat16*)(d0 + WIMG + off) = lb;
    }
}

// ---------------- Wp image builder for out -------------------------------------
__global__ __launch_bounds__(256) void wpsplit_kernel(const float* __restrict__ Wp) {
    int chunk = blockIdx.x;   // 0..7
    int ntile = blockIdx.y;   // 0..5
    int tid = threadIdx.x;
    int rr = tid >> 2;
    int q  = tid & 3;
    int n = ntile * 64 + rr;
    unsigned char* d0 = g_WPe + ((size_t)(ntile * 8 + chunk) * 2) * WIMG;
    #pragma unroll
    for (int c = 0; c < 18; c++) {
        int col = q * 18 + c;
        int k = chunk * 64 + col;
        float v = (col < 64 && n < CIN) ? Wp[(size_t)n * DM + k] : 0.f;
        __nv_bfloat16 hb = __float2bfloat16(v);
        float rem2 = v - __bfloat162float(hb);
        __nv_bfloat16 lb = __float2bfloat16(rem2);
        size_t off = (size_t)rr * 144 + col * 2;
        *(__nv_bfloat16*)(d0 + off)        = hb;
        *(__nv_bfloat16*)(d0 + WIMG + off) = lb;
    }
}

// ---------------- x normalize+split images -------------------------------------
__global__ __launch_bounds__(256) void xsplit_kernel(const float* __restrict__ x) {
    int idx = blockIdx.x * 256 + threadIdx.x;
    if (idx >= BATCH * TSEQ * CIN) return;
    int m = idx / CIN, k = idx - m * CIN;
    int b = m / TSEQ;
    int bc = b * CIN + k;
    float v = (x[idx] - g_mean[bc]) * g_istd[bc];
    __nv_bfloat16 hb = __float2bfloat16(v);
    float rem = v - __bfloat162float(hb);
    __nv_bfloat16 lb = __float2bfloat16(rem);
    int chunk = k >> 6, col = k & 63;
    size_t offh = ((size_t)(chunk * 2) * 24576 + m) * 144 + col * 2;
    *(__nv_bfloat16*)(g_Xbf + offh)        = hb;
    *(__nv_bfloat16*)(g_Xbf + offh + XIMG) = lb;
}

// ---------------- init ----------------------------------------------------------
__global__ __launch_bounds__(256) void init_kernel() {
    int i = blockIdx.x * 256 + threadIdx.x;
    if (i < (int)(sizeof(g_Hbf) / 4)) ((uint32_t*)g_Hbf)[i] = 0u;
    if (i < NSTEP * 4 * 32) g_bar2[i] = 0u;
}

// ---------------- gx = xnorm @ Wih^T via HMMA split ----------------------------
#define GXSTAGE 55296
#define GX_SMEM (2*GXSTAGE)
__global__ void __launch_bounds__(256, 1) gxmma_kernel() {
    extern __shared__ unsigned char smem[];
    const int tid = threadIdx.x;
    const int w = tid >> 5, lane = tid & 31;
    const int n0 = blockIdx.x * 64;
    const int m0 = blockIdx.y * 128;
    uint32_t sbase = smem_u32(smem);
    float acc[8][4];
    #pragma unroll
    for (int f = 0; f < 8; f++)
        #pragma unroll
        for (int r = 0; r < 4; r++) acc[f][r] = 0.f;

    const uint32_t aoff = (uint32_t)((w * 16 + (lane & 15)) * 144 + (lane >> 4) * 16);
    const uint32_t boff = (uint32_t)(((((lane >> 4) & 1) * 8) + (lane & 7)) * 144 + ((lane >> 3) & 1) * 16);
    const unsigned char* Bbase = g_WIe + ((size_t)blockIdx.x * 6 * 2) * WIMG;

    auto issue = [&](int chunk, int buf) {
        uint32_t sb = sbase + buf * GXSTAGE;
        #pragma unroll
        for (int i = 0; i < 14; i++) {
            int idx = tid + i * 256;
            if (idx >= 3456) break;
            uint32_t dst; const unsigned char* src;
            if (idx < 2304) {
                int sp = idx / 1152; int off = (idx - sp * 1152) * 16;
                dst = sb + sp * 18432 + off;
                src = g_Xbf + (size_t)(chunk * 2 + sp) * XIMG + (size_t)m0 * 144 + off;
            } else {
                int j = idx - 2304; int sp = j / 576; int off = (j - sp * 576) * 16;
                dst = sb + 36864 + sp * 9216 + off;
                src = Bbase + (size_t)(chunk * 2 + sp) * WIMG + off;
            }
            cpasync16(dst, src);
        }
        CP_COMMIT();
    };

    issue(0, 0); issue(1, 1);
    #pragma unroll 1
    for (int c = 0; c < 6; c++) {
        if (c < 5) { CP_WAIT(1); } else { CP_WAIT(0); }
        __syncthreads();
        uint32_t st = sbase + (c & 1) * GXSTAGE;
        uint32_t sAhi = st, sAlo = st + 18432, sWhi = st + 36864, sWlo = st + 46080;
        #pragma unroll
        for (int kf = 0; kf < 4; kf++) {
            uint32_t ah[4], al[4], bh[4][4], bl[4][4];
            ldsm4(ah, sAhi + aoff + kf * 32);
            ldsm4(al, sAlo + aoff + kf * 32);
            #pragma unroll
            for (int ng = 0; ng < 4; ng++) {
                ldsm4(bh[ng], sWhi + boff + ng * 2304 + kf * 32);
                ldsm4(bl[ng], sWlo + boff + ng * 2304 + kf * 32);
            }
            #pragma unroll
            for (int ng = 0; ng < 4; ng++) { mma16816(acc[2*ng], ah, bh[ng]); mma16816(acc[2*ng+1], ah, bh[ng]+2); }
            #pragma unroll
            for (int ng = 0; ng < 4; ng++) { mma16816(acc[2*ng], ah, bl[ng]); mma16816(acc[2*ng+1], ah, bl[ng]+2); }
            #pragma unroll
            for (int ng = 0; ng < 4; ng++) { mma16816(acc[2*ng], al, bh[ng]); mma16816(acc[2*ng+1], al, bh[ng]+2); }
        }
        __syncthreads();
        if (c + 2 < 6) issue(c + 2, c & 1);
    }
    #pragma unroll
    for (int f = 0; f < 8; f++) {
        int n = n0 + (f >> 1) * 16 + (f & 1) * 8 + (lane & 3) * 2;
        #pragma unroll
        for (int rowi = 0; rowi < 2; rowi++) {
            int m = m0 + w * 16 + (lane >> 2) + rowi * 8;
            *(float2*)&g_Gx[(size_t)m * G4 + n] = make_float2(acc[f][rowi*2], acc[f][rowi*2+1]);
        }
    }
}

// ---------------- persistent LSTM kernel (bf16 3-term, pipelined fragments) ----
#define WCACHE_B 147456
#define ABUF_B   18432
#define PERSIST_SMEM (WCACHE_B + 3*ABUF_B)

__global__ void __launch_bounds__(256, 1) persist_kernel(const float* __restrict__ gx,
                                                         const float* __restrict__ benc,
                                                         const float* __restrict__ bd) {
    extern __shared__ unsigned char smem[];
    const int tid = threadIdx.x;
    const int w = tid >> 5, lane = tid & 31;
    const int wr = w & 3, wc = w >> 2;
    const int ntile = blockIdx.x, mq = blockIdx.y;
    uint32_t sbase = smem_u32(smem);
    uint32_t Wc = sbase;
    uint32_t Ab = sbase + WCACHE_B;

    const uint32_t aoff = (uint32_t)((wr * 16 + (lane & 15)) * 144 + (lane >> 4) * 16);
    const uint32_t boff = (uint32_t)((wc * 32 + ((lane >> 4) & 1) * 8 + (lane & 7)) * 144 + ((lane >> 3) & 1) * 16);

    const unsigned char* WEsrc = g_WTe + ((size_t)(ntile * 8) * 2) * WIMG;
    const unsigned char* WDsrc = g_WTd + ((size_t)(ntile * 8) * 2) * WIMG;

    auto loadW = [&](const unsigned char* src) {
        #pragma unroll 4
        for (int i = 0; i < 36; i++) {
            int idx = tid + i * 256;
            int img = idx / 576;
            int off = (idx - img * 576) * 16;
            cpasync16(Wc + img * 9216 + off, src + (size_t)img * WIMG + off);
        }
        CP_COMMIT();
    };
    auto loadA = [&](const unsigned char* Apar, int chunk, int buf) {
        #pragma unroll
        for (int i = 0; i < 5; i++) {
            int idx = tid + i * 256;
            if (idx < 1152) {
                int split = idx / 576;
                int off = (idx - split * 576) * 16;
                cpasync16(Ab + buf * ABUF_B + split * 9216 + off,
                          Apar + (size_t)(chunk * 2 + split) * AIMG + mq * 9216 + off);
            }
        }
        CP_COMMIT();
    };

    const int j0 = ntile * 16 + wc * 8 + (lane & 3) * 2;
    const int bbase = mq * 64 + wr * 16 + (lane >> 2);
    const int chunkA = ntile >> 2;
    const size_t colOff = (size_t)((ntile & 3) * 16 + wc * 8 + (lane & 3) * 2) * 2;

    float bi[4][2];
    #pragma unroll
    for (int g = 0; g < 4; g++) { bi[g][0] = benc[g * DM + j0]; bi[g][1] = benc[g * DM + j0 + 1]; }
    float creg[4] = {0.f, 0.f, 0.f, 0.f};

    loadW(WEsrc);
    CP_WAIT(0);
    __syncthreads();

    for (int s = 0; s < NSTEP; s++) {
        const bool enc = (s < TSEQ);
        if (s == TSEQ) {
            __syncthreads();
            loadW(WDsrc);
            #pragma unroll
            for (int g = 0; g < 4; g++) { bi[g][0] = bd[g * DM + j0]; bi[g][1] = bd[g * DM + j0 + 1]; }
            CP_WAIT(0);
            __syncthreads();
        }
        const int par = s & 1;
        const unsigned char* Apar = g_Hbf + (size_t)(par * 16) * AIMG;

        float pr[16];
        if (enc) {
            #pragma unroll
            for (int rowi = 0; rowi < 2; rowi++) {
                const float* gr = gx + ((size_t)(bbase + rowi * 8) * TSEQ + s) * G4;
                #pragma unroll
                for (int g = 0; g < 4; g++) {
                    float2 v = *(const float2*)&gr[g * DM + j0];
                    pr[rowi * 8 + g * 2]     = v.x;
                    pr[rowi * 8 + g * 2 + 1] = v.y;
                }
            }
        }

        float acc[4][4];
        #pragma unroll
        for (int g = 0; g < 4; g++)
            #pragma unroll
            for (int r = 0; r < 4; r++) acc[g][r] = 0.f;

        if (s > 0) {    // s==0: h=0, MMA result is all zeros — skip loads+MMA entirely
            loadA(Apar, 0, 0);
            loadA(Apar, 1, 1);
            #pragma unroll 1
            for (int c = 0; c < 8; c++) {
                if (c + 2 < 8) { loadA(Apar, c + 2, (c + 2) % 3); CP_WAIT(2); }
                else if (c == 6) { CP_WAIT(1); }
                else if (c == 7) { CP_WAIT(0); }
                __syncthreads();
                uint32_t at = Ab + (c % 3) * ABUF_B;
                uint32_t sAhi = at, sAlo = at + 9216;
                uint32_t wt = Wc + c * 18432;
                uint32_t sWhi = wt, sWlo = wt + 9216;

                // preload ALL A fragments for this chunk (latencies overlap)
                uint32_t AH[4][4], AL[4][4];
                #pragma unroll
                for (int kf = 0; kf < 4; kf++) {
                    ldsm4(AH[kf], sAhi + aoff + kf * 32);
                    ldsm4(AL[kf], sAlo + aoff + kf * 32);
                }
                // W fragments double-buffered across kf
                uint32_t WB[2][4][4];
                ldsm4(WB[0][0], sWhi + boff);
                ldsm4(WB[0][1], sWhi + boff + 2304);
                ldsm4(WB[0][2], sWlo + boff);
                ldsm4(WB[0][3], sWlo + boff + 2304);
                #pragma unroll
                for (int kf = 0; kf < 4; kf++) {
                    const int cur = kf & 1, nxt = cur ^ 1;
                    if (kf < 3) {
                        ldsm4(WB[nxt][0], sWhi + boff + (kf + 1) * 32);
                        ldsm4(WB[nxt][1], sWhi + boff + 2304 + (kf + 1) * 32);
                        ldsm4(WB[nxt][2], sWlo + boff + (kf + 1) * 32);
                        ldsm4(WB[nxt][3], sWlo + boff + 2304 + (kf + 1) * 32);
                    }
                    const uint32_t* ah = AH[kf];
                    const uint32_t* al = AL[kf];
                    mma16816(acc[0], ah, WB[cur][0]); mma16816(acc[1], ah, WB[cur][0] + 2);
                    mma16816(acc[2], ah, WB[cur][1]); mma16816(acc[3], ah, WB[cur][1] + 2);
                    mma16816(acc[0], ah, WB[cur][2]); mma16816(acc[1], ah, WB[cur][2] + 2);
                    mma16816(acc[2], ah, WB[cur][3]); mma16816(acc[3], ah, WB[cur][3] + 2);
                    mma16816(acc[0], al, WB[cur][0]); mma16816(acc[1], al, WB[cur][0] + 2);
                    mma16816(acc[2], al, WB[cur][1]); mma16816(acc[3], al, WB[cur][1] + 2);
                }
                __syncthreads();
            }
        }

        // ---- epilogue ----
        unsigned char* imgHi = g_Hbf + (size_t)(((par ^ 1) * 8 + chunkA) * 2) * AIMG;
        unsigned char* imgLo = imgHi + AIMG;
        unsigned char* decHi = nullptr;
        if (s >= TSEQ - 1) {
            int d = s - (TSEQ - 1);
            decHi = g_Dbf + (size_t)((d * 8 + chunkA) * 2) * AIMG;
        }

        #pragma unroll
        for (int rowi = 0; rowi < 2; rowi++) {
            int b = bbase + rowi * 8;
            float h2[2];
            #pragma unroll
            for (int cp = 0; cp < 2; cp++) {
                float gi = acc[0][rowi * 2 + cp] + bi[0][cp];
                float gf = acc[1][rowi * 2 + cp] + bi[1][cp];
                float gg = acc[2][rowi * 2 + cp] + bi[2][cp];
                float go = acc[3][rowi * 2 + cp] + bi[3][cp];
                if (enc) {
                    gi += pr[rowi * 8 + 0 + cp];
                    gf += pr[rowi * 8 + 2 + cp];
                    gg += pr[rowi * 8 + 4 + cp];
                    go += pr[rowi * 8 + 6 + cp];
                }
                float cn = fsig(gf) * creg[rowi * 2 + cp] + fsig(gi) * ftanh(gg);
                float hn = fsig(go) * ftanh(cn);
                creg[rowi * 2 + cp] = cn;
                h2[cp] = hn;
            }
            uint32_t hw, lw;
            bfsplit2(h2[0], h2[1], hw, lw);
            size_t off = (size_t)b * 144 + colOff;
            *(uint32_t*)(imgHi + off) = hw;
            *(uint32_t*)(imgLo + off) = lw;
            if (decHi) {
                *(uint32_t*)(decHi + off) = hw;
                *(uint32_t*)(decHi + AIMG + off) = lw;
            }
        }

        // ---- per-mq grid barrier (32 blocks, padded counter) ----
        if (s < NSTEP - 1) {
            __threadfence();
            __syncthreads();
            if (tid == 0) {
                unsigned* p = &g_bar2[(s * 4 + mq) * 32];
                unsigned prev = atomicAdd(p, 1u);
                if (prev != 31u) {
                    unsigned v;
                    do {
                        asm volatile("ld.acquire.gpu.u32 %0, [%1];" : "=r"(v) : "l"(p) : "memory");
                    } while (v < 32u);
                }
            }
            __syncthreads();
        }
    }
}

// ---------------- out: Y = Dbf @ Wp^T via HMMA, denormalize, scatter -----------
#define OSTAGE 55296
#define OUT_SMEM (2*OSTAGE)
__global__ void __launch_bounds__(256, 1) outmma_kernel(const float* __restrict__ bp,
                                                        float* __restrict__ out) {
    extern __shared__ unsigned char smem[];
    const int tid = threadIdx.x;
    const int w = tid >> 5, lane = tid & 31;
    const int ntile = blockIdx.x;        // 0..5
    const int mt = blockIdx.y;           // 0..191
    const int d = mt >> 1, half = mt & 1;
    const int m0 = half * 128;
    uint32_t sbase = smem_u32(smem);
    float acc[8][4];
    #pragma unroll
    for (int f = 0; f < 8; f++)
        #pragma unroll
        for (int r = 0; r < 4; r++) acc[f][r] = 0.f;

    const uint32_t aoff = (uint32_t)((w * 16 + (lane & 15)) * 144 + (lane >> 4) * 16);
    const uint32_t boff = (uint32_t)(((((lane >> 4) & 1) * 8) + (lane & 7)) * 144 + ((lane >> 3) & 1) * 16);
    const unsigned char* Abase = g_Dbf + (size_t)(d * 16) * AIMG;
    const unsigned char* Bbase = g_WPe + ((size_t)(ntile * 8) * 2) * WIMG;

    auto issue = [&](int chunk, int buf) {
        uint32_t sb = sbase + buf * OSTAGE;
        #pragma unroll
        for (int i = 0; i < 14; i++) {
            int idx = tid + i * 256;
            if (idx >= 3456) break;
            uint32_t dst; const unsigned char* src;
            if (idx < 2304) {
                int sp = idx / 1152; int off = (idx - sp * 1152) * 16;
                dst = sb + sp * 18432 + off;
                src = Abase + (size_t)(chunk * 2 + sp) * AIMG + (size_t)m0 * 144 + off;
            } else {
                int j = idx - 2304; int sp = j / 576; int off = (j - sp * 576) * 16;
                dst = sb + 36864 + sp * 9216 + off;
                src = Bbase + (size_t)(chunk * 2 + sp) * WIMG + off;
            }
            cpasync16(dst, src);
        }
        CP_COMMIT();
    };

    issue(0, 0); issue(1, 1);
    #pragma unroll 1
    for (int c = 0; c < 8; c++) {
        if (c < 7) { CP_WAIT(1); } else { CP_WAIT(0); }
        __syncthreads();
        uint32_t st = sbase + (c & 1) * OSTAGE;
        uint32_t sAhi = st, sAlo = st + 18432, sWhi = st + 36864, sWlo = st + 46080;
        #pragma unroll
        for (int kf = 0; kf < 4; kf++) {
            uint32_t ah[4], al[4], bh[4][4], bl[4][4];
            ldsm4(ah, sAhi + aoff + kf * 32);
            ldsm4(al, sAlo + aoff + kf * 32);
            #pragma unroll
            for (int ng = 0; ng < 4; ng++) {
                ldsm4(bh[ng], sWhi + boff + ng * 2304 + kf * 32);
                ldsm4(bl[ng], sWlo + boff + ng * 2304 + kf * 32);
            }
            #pragma unroll
            for (int ng = 0; ng < 4; ng++) { mma16816(acc[2*ng], ah, bh[ng]); mma16816(acc[2*ng+1], ah, bh[ng]+2); }
            #pragma unroll
            for (int ng = 0; ng < 4; ng++) { mma16816(acc[2*ng], ah, bl[ng]); mma16816(acc[2*ng+1], ah, bl[ng]+2); }
            #pragma unroll
            for (int ng = 0; ng < 4; ng++) { mma16816(acc[2*ng], al, bh[ng]); mma16816(acc[2*ng+1], al, bh[ng]+2); }
        }
        __syncthreads();
        if (c + 2 < 8) issue(c + 2, c & 1);
    }
    #pragma unroll
    for (int f = 0; f < 8; f++) {
        int gn = ntile * 64 + (f >> 1) * 16 + (f & 1) * 8 + (lane & 3) * 2;
        #pragma unroll
        for (int rowi = 0; rowi < 2; rowi++) {
            int b = m0 + w * 16 + (lane >> 2) + rowi * 8;
            #pragma unroll
            for (int cp = 0; cp < 2; cp++) {
                int n = gn + cp;
                if (n < CIN) {
                    int bc = b * CIN + n;
                    float y = acc[f][rowi * 2 + cp] + bp[n];
                    out[(size_t)b * PRED * CIN + (size_t)d * CIN + n] =
                        y * g_std[bc] + g_mean[bc];
                }
            }
        }
    }
}

// ---------------- host launcher ------------------------------------------------
extern "C" void kernel_launch(void* const* d_in, const int* in_sizes, int n_in,
                              void* d_out, int out_size) {
    const float* x   = (const float*)d_in[0];
    const float* Wih = (const float*)d_in[1];
    const float* Whh = (const float*)d_in[2];
    const float* bih = (const float*)d_in[3];
    const float* bhh = (const float*)d_in[4];
    const float* Wp  = (const float*)d_in[5];
    const float* bp  = (const float*)d_in[6];
    float* out = (float*)d_out;

    float *gx, *wd, *bd, *benc;
    unsigned char *wte, *wtd;
    cudaGetSymbolAddress((void**)&gx,   g_Gx);
    cudaGetSymbolAddress((void**)&wd,   g_Wd);
    cudaGetSymbolAddress((void**)&bd,   g_bd);
    cudaGetSymbolAddress((void**)&benc, g_benc);
    cudaGetSymbolAddress((void**)&wte,  g_WTe);
    cudaGetSymbolAddress((void**)&wtd,  g_WTd);

    cudaFuncSetAttribute(persist_kernel, cudaFuncAttributeMaxDynamicSharedMemorySize, PERSIST_SMEM);
    cudaFuncSetAttribute(gxmma_kernel, cudaFuncAttributeMaxDynamicSharedMemorySize, GX_SMEM);
    cudaFuncSetAttribute(outmma_kernel, cudaFuncAttributeMaxDynamicSharedMemorySize, OUT_SMEM);

    stats_kernel<<<(BATCH * CIN + 255) / 256, 256>>>(x);
    bias_kernel<<<(G4 + 255) / 256, 256>>>(bih, bhh, Wih, bp);
    wd_kernel<<<dim3(DM / 64, G4 / 64), 256>>>(Wih, Wp, Whh);
    xsplit_kernel<<<(BATCH * TSEQ * CIN + 255) / 256, 256>>>(x);
    wihsplit_kernel<<<dim3(6, 32), 256>>>(Wih);
    wpsplit_kernel<<<dim3(8, 6), 256>>>(Wp);
    wsplit_kernel<<<dim3(8, 32), 256>>>(Whh, wte);
    wsplit_kernel<<<dim3(8, 32), 256>>>(wd, wtd);
    init_kernel<<<((int)(sizeof(g_Hbf) / 4) + 255) / 256, 256>>>();
    gxmma_kernel<<<dim3(32, 192), 256, GX_SMEM>>>();

    persist_kernel<<<dim3(32, 4), 256, PERSIST_SMEM>>>(gx, benc, bd);

    outmma_kernel<<<dim3(6, 192), 256, OUT_SMEM>>>(bp, out);
    (void)in_sizes; (void)n_in; (void)out_size;
}

// round 13
// speedup vs baseline: 2.0208x; 1.0040x over previous
#include <cuda_runtime.h>
#include <cuda_bf16.h>
#include <math.h>
#include <stdint.h>

#define BATCH 256
#define TSEQ  96
#define PRED  96
#define CIN   321
#define DM    512
#define G4    2048
#define HD    (BATCH*DM)
#define NSTEP (TSEQ+PRED-1)     // 191

#define AIMG  36864u            // bf16 image: 256 rows x 144 B per (chunk,split)
#define WIMG  9216u             // bf16 W image: 64 rows x 144 B
#define XIMG  (24576u*144u)

// ---------------- device scratch ----------------------------------------------
__device__ float g_mean[BATCH*CIN];
__device__ float g_std [BATCH*CIN];
__device__ float g_istd[BATCH*CIN];
__device__ float g_Gx  [(size_t)BATCH*TSEQ*G4];
__device__ float g_Wd  [G4*DM];
__device__ float g_bd  [G4];
__device__ float g_benc[G4];
__device__ unsigned g_bar2[NSTEP*4*32];           // per (step,mq) counter, 128B padded
// bf16 hidden images: [par2][chunk8][split2][256][72]
__device__ __align__(1024) unsigned char g_Hbf[2*8*2*AIMG];
// decoder hidden bf16 split images: [d96][chunk8][split2][256][72]
__device__ __align__(1024) unsigned char g_Dbf[(size_t)96*8*2*AIMG];
// recurrent W images: [ntile32][chunk8][split2][64][72]
__device__ __align__(1024) unsigned char g_WTe[32*8*2*WIMG];
__device__ __align__(1024) unsigned char g_WTd[32*8*2*WIMG];
// gx operand images
__device__ __align__(1024) unsigned char g_Xbf[6*2*XIMG];
__device__ __align__(1024) unsigned char g_WIe[32*6*2*WIMG];
// Wp images for out: [ntile6][chunk8][split2][64][72]
__device__ __align__(1024) unsigned char g_WPe[6*8*2*WIMG];

// ---------------- helpers ------------------------------------------------------
__device__ __forceinline__ float sigf(float x) { return 1.f / (1.f + expf(-x)); }
// branchless fast gates for the persistent kernel (error ~1e-6, MUFU-only)
__device__ __forceinline__ float fsig(float x) {
    return __fdividef(1.f, 1.f + __expf(-x));
}
__device__ __forceinline__ float ftanh(float x) {
    return __fdividef(2.f, 1.f + __expf(-2.f * x)) - 1.f;
}

__device__ __forceinline__ uint32_t smem_u32(const void* p) {
    uint32_t a;
    asm("{ .reg .u64 t; cvta.to.shared.u64 t, %1; cvt.u32.u64 %0, t; }" : "=r"(a) : "l"(p));
    return a;
}
__device__ __forceinline__ void cpasync16(uint32_t dst, const void* src) {
    asm volatile("cp.async.cg.shared.global [%0], [%1], 16;" :: "r"(dst), "l"(src) : "memory");
}
#define CP_COMMIT() asm volatile("cp.async.commit_group;" ::: "memory")
#define CP_WAIT(N)  asm volatile("cp.async.wait_group %0;" :: "n"(N) : "memory")

__device__ __forceinline__ void ldsm4(uint32_t* r, uint32_t addr) {
    asm volatile("ldmatrix.sync.aligned.m8n8.x4.shared.b16 {%0,%1,%2,%3}, [%4];"
        : "=r"(r[0]), "=r"(r[1]), "=r"(r[2]), "=r"(r[3]) : "r"(addr));
}
__device__ __forceinline__ void mma16816(float* d, const uint32_t* a, const uint32_t* b) {
    asm volatile("mma.sync.aligned.m16n8k16.row.col.f32.bf16.bf16.f32 "
        "{%0,%1,%2,%3}, {%4,%5,%6,%7}, {%8,%9}, {%0,%1,%2,%3};"
        : "+f"(d[0]), "+f"(d[1]), "+f"(d[2]), "+f"(d[3])
        : "r"(a[0]), "r"(a[1]), "r"(a[2]), "r"(a[3]), "r"(b[0]), "r"(b[1]));
}
__device__ __forceinline__ void bfsplit2(float a, float b, uint32_t& hw, uint32_t& lw) {
    __nv_bfloat16 h0 = __float2bfloat16(a), h1 = __float2bfloat16(b);
    float r0 = a - __bfloat162float(h0), r1 = b - __bfloat162float(h1);
    __nv_bfloat16 l0 = __float2bfloat16(r0), l1 = __float2bfloat16(r1);
    hw = (uint32_t)__bfloat16_as_ushort(h0) | ((uint32_t)__bfloat16_as_ushort(h1) << 16);
    lw = (uint32_t)__bfloat16_as_ushort(l0) | ((uint32_t)__bfloat16_as_ushort(l1) << 16);
}

// ---------------- stats --------------------------------------------------------
__global__ __launch_bounds__(256) void stats_kernel(const float* __restrict__ x) {
    int idx = blockIdx.x * 256 + threadIdx.x;
    if (idx >= BATCH * CIN) return;
    int b = idx / CIN, ch = idx % CIN;
    float s = 0.f, ss = 0.f;
    const float* p = x + (size_t)b * TSEQ * CIN + ch;
    #pragma unroll 4
    for (int t = 0; t < TSEQ; t++) { float v = p[t * CIN]; s += v; ss += v * v; }
    float mean = s * (1.f / TSEQ);
    float var = ss * (1.f / TSEQ) - mean * mean;
    if (var < 0.f) var = 0.f;
    float sd = sqrtf(var + 1e-5f);
    g_mean[idx] = mean; g_std[idx] = sd; g_istd[idx] = 1.f / sd;
}

// ---------------- bias fold ----------------------------------------------------
__global__ __launch_bounds__(256) void bias_kernel(const float* __restrict__ bih,
                                                   const float* __restrict__ bhh,
                                                   const float* __restrict__ Wih,
                                                   const float* __restrict__ bp) {
    int n = blockIdx.x * 256 + threadIdx.x;
    if (n >= G4) return;
    float be = bih[n] + bhh[n];
    float s = 0.f;
    const float* w = Wih + (size_t)n * CIN;
    for (int j = 0; j < CIN; j++) s += w[j] * bp[j];
    g_benc[n] = be;
    g_bd[n] = be + s;
}

// ---------------- Wd = Whh + Wih @ Wp ------------------------------------------
__global__ __launch_bounds__(256) void wd_kernel(const float* __restrict__ Wih,
                                                 const float* __restrict__ Wp,
                                                 const float* __restrict__ Whh) {
    __shared__ float As[64 * 17];
    __shared__ float Bs[16 * 65];
    int tid = threadIdx.x;
    int n0 = blockIdx.x * 64;
    int m0 = blockIdx.y * 64;
    int tr = tid >> 4, tc = tid & 15;
    float acc[4][4] = {};
    for (int j0 = 0; j0 < CIN; j0 += 16) {
        #pragma unroll
        for (int i = 0; i < 4; i++) {
            int l = tid + 256 * i;
            int mr = l >> 4, jj = l & 15;
            int j = j0 + jj;
            As[mr * 17 + jj] = (j < CIN) ? Wih[(size_t)(m0 + mr) * CIN + j] : 0.f;
        }
        #pragma unroll
        for (int i = 0; i < 4; i++) {
            int l = tid + 256 * i;
            int jj = l >> 6, nr = l & 63;
            int j = j0 + jj;
            Bs[jj * 65 + nr] = (j < CIN) ? Wp[(size_t)j * DM + n0 + nr] : 0.f;
        }
        __syncthreads();
        #pragma unroll
        for (int jj = 0; jj < 16; jj++) {
            float a[4], bb[4];
            #pragma unroll
            for (int r = 0; r < 4; r++) a[r] = As[(tr * 4 + r) * 17 + jj];
            #pragma unroll
            for (int cc = 0; cc < 4; cc++) bb[cc] = Bs[jj * 65 + tc * 4 + cc];
            #pragma unroll
            for (int r = 0; r < 4; r++)
                #pragma unroll
                for (int cc = 0; cc < 4; cc++) acc[r][cc] += a[r] * bb[cc];
        }
        __syncthreads();
    }
    #pragma unroll
    for (int r = 0; r < 4; r++) {
        int m = m0 + tr * 4 + r;
        #pragma unroll
        for (int cc = 0; cc < 4; cc++) {
            int n = n0 + tc * 4 + cc;
            g_Wd[(size_t)m * DM + n] = Whh[(size_t)m * DM + n] + acc[r][cc];
        }
    }
}

// ---------------- recurrent W image builder ------------------------------------
__global__ __launch_bounds__(256) void wsplit_kernel(const float* __restrict__ src,
                                                     unsigned char* __restrict__ dst) {
    int chunk = blockIdx.x;
    int ntile = blockIdx.y;
    int tid = threadIdx.x;
    int rr = tid >> 2;
    int q  = tid & 3;
    int joct = rr >> 5, rem = rr & 31;
    int gate = rem >> 3, j7 = rem & 7;
    int srow = gate * DM + ntile * 16 + joct * 8 + j7;
    unsigned char* d0 = dst + ((size_t)(ntile * 8 + chunk) * 2) * WIMG;
    #pragma unroll
    for (int c = 0; c < 18; c++) {
        int col = q * 18 + c;
        float v = (col < 64) ? src[(size_t)srow * DM + chunk * 64 + col] : 0.f;
        __nv_bfloat16 hb = __float2bfloat16(v);
        float rem2 = v - __bfloat162float(hb);
        __nv_bfloat16 lb = __float2bfloat16(rem2);
        size_t off = (size_t)rr * 144 + col * 2;
        *(__nv_bfloat16*)(d0 + off)        = hb;
        *(__nv_bfloat16*)(d0 + WIMG + off) = lb;
    }
}

// ---------------- Wih image builder for gx -------------------------------------
__global__ __launch_bounds__(256) void wihsplit_kernel(const float* __restrict__ Wih) {
    int chunk = blockIdx.x;
    int ntile = blockIdx.y;
    int tid = threadIdx.x;
    int rr = tid >> 2;
    int q  = tid & 3;
    int srow = ntile * 64 + rr;
    unsigned char* d0 = g_WIe + ((size_t)(ntile * 6 + chunk) * 2) * WIMG;
    #pragma unroll
    for (int c = 0; c < 18; c++) {
        int col = q * 18 + c;
        int k = chunk * 64 + col;
        float v = (col < 64 && k < CIN) ? Wih[(size_t)srow * CIN + k] : 0.f;
        __nv_bfloat16 hb = __float2bfloat16(v);
        float rem2 = v - __bfloat162float(hb);
        __nv_bfloat16 lb = __float2bfloat16(rem2);
        size_t off = (size_t)rr * 144 + col * 2;
        *(__nv_bfloat16*)(d0 + off)        = hb;
        *(__nv_bfloat16*)(d0 + WIMG + off) = lb;
    }
}

// ---------------- Wp image builder for out -------------------------------------
__global__ __launch_bounds__(256) void wpsplit_kernel(const float* __restrict__ Wp) {
    int chunk = blockIdx.x;   // 0..7
    int ntile = blockIdx.y;   // 0..5
    int tid = threadIdx.x;
    int rr = tid >> 2;
    int q  = tid & 3;
    int n = ntile * 64 + rr;
    unsigned char* d0 = g_WPe + ((size_t)(ntile * 8 + chunk) * 2) * WIMG;
    #pragma unroll
    for (int c = 0; c < 18; c++) {
        int col = q * 18 + c;
        int k = chunk * 64 + col;
        float v = (col < 64 && n < CIN) ? Wp[(size_t)n * DM + k] : 0.f;
        __nv_bfloat16 hb = __float2bfloat16(v);
        float rem2 = v - __bfloat162float(hb);
        __nv_bfloat16 lb = __float2bfloat16(rem2);
        size_t off = (size_t)rr * 144 + col * 2;
        *(__nv_bfloat16*)(d0 + off)        = hb;
        *(__nv_bfloat16*)(d0 + WIMG + off) = lb;
    }
}

// ---------------- x normalize+split images -------------------------------------
__global__ __launch_bounds__(256) void xsplit_kernel(const float* __restrict__ x) {
    int idx = blockIdx.x * 256 + threadIdx.x;
    if (idx >= BATCH * TSEQ * CIN) return;
    int m = idx / CIN, k = idx - m * CIN;
    int b = m / TSEQ;
    int bc = b * CIN + k;
    float v = (x[idx] - g_mean[bc]) * g_istd[bc];
    __nv_bfloat16 hb = __float2bfloat16(v);
    float rem = v - __bfloat162float(hb);
    __nv_bfloat16 lb = __float2bfloat16(rem);
    int chunk = k >> 6, col = k & 63;
    size_t offh = ((size_t)(chunk * 2) * 24576 + m) * 144 + col * 2;
    *(__nv_bfloat16*)(g_Xbf + offh)        = hb;
    *(__nv_bfloat16*)(g_Xbf + offh + XIMG) = lb;
}

// ---------------- init ----------------------------------------------------------
__global__ __launch_bounds__(256) void init_kernel() {
    int i = blockIdx.x * 256 + threadIdx.x;
    if (i < (int)(sizeof(g_Hbf) / 4)) ((uint32_t*)g_Hbf)[i] = 0u;
    if (i < NSTEP * 4 * 32) g_bar2[i] = 0u;
}

// ---------------- gx = xnorm @ Wih^T via HMMA split ----------------------------
#define GXSTAGE 55296
#define GX_SMEM (2*GXSTAGE)
__global__ void __launch_bounds__(256, 1) gxmma_kernel() {
    extern __shared__ unsigned char smem[];
    const int tid = threadIdx.x;
    const int w = tid >> 5, lane = tid & 31;
    const int n0 = blockIdx.x * 64;
    const int m0 = blockIdx.y * 128;
    uint32_t sbase = smem_u32(smem);
    float acc[8][4];
    #pragma unroll
    for (int f = 0; f < 8; f++)
        #pragma unroll
        for (int r = 0; r < 4; r++) acc[f][r] = 0.f;

    const uint32_t aoff = (uint32_t)((w * 16 + (lane & 15)) * 144 + (lane >> 4) * 16);
    const uint32_t boff = (uint32_t)(((((lane >> 4) & 1) * 8) + (lane & 7)) * 144 + ((lane >> 3) & 1) * 16);
    const unsigned char* Bbase = g_WIe + ((size_t)blockIdx.x * 6 * 2) * WIMG;

    auto issue = [&](int chunk, int buf) {
        uint32_t sb = sbase + buf * GXSTAGE;
        #pragma unroll
        for (int i = 0; i < 14; i++) {
            int idx = tid + i * 256;
            if (idx >= 3456) break;
            uint32_t dst; const unsigned char* src;
            if (idx < 2304) {
                int sp = idx / 1152; int off = (idx - sp * 1152) * 16;
                dst = sb + sp * 18432 + off;
                src = g_Xbf + (size_t)(chunk * 2 + sp) * XIMG + (size_t)m0 * 144 + off;
            } else {
                int j = idx - 2304; int sp = j / 576; int off = (j - sp * 576) * 16;
                dst = sb + 36864 + sp * 9216 + off;
                src = Bbase + (size_t)(chunk * 2 + sp) * WIMG + off;
            }
            cpasync16(dst, src);
        }
        CP_COMMIT();
    };

    issue(0, 0); issue(1, 1);
    #pragma unroll 1
    for (int c = 0; c < 6; c++) {
        if (c < 5) { CP_WAIT(1); } else { CP_WAIT(0); }
        __syncthreads();
        uint32_t st = sbase + (c & 1) * GXSTAGE;
        uint32_t sAhi = st, sAlo = st + 18432, sWhi = st + 36864, sWlo = st + 46080;
        #pragma unroll
        for (int kf = 0; kf < 4; kf++) {
            uint32_t ah[4], al[4], bh[4][4], bl[4][4];
            ldsm4(ah, sAhi + aoff + kf * 32);
            ldsm4(al, sAlo + aoff + kf * 32);
            #pragma unroll
            for (int ng = 0; ng < 4; ng++) {
                ldsm4(bh[ng], sWhi + boff + ng * 2304 + kf * 32);
                ldsm4(bl[ng], sWlo + boff + ng * 2304 + kf * 32);
            }
            #pragma unroll
            for (int ng = 0; ng < 4; ng++) { mma16816(acc[2*ng], ah, bh[ng]); mma16816(acc[2*ng+1], ah, bh[ng]+2); }
            #pragma unroll
            for (int ng = 0; ng < 4; ng++) { mma16816(acc[2*ng], ah, bl[ng]); mma16816(acc[2*ng+1], ah, bl[ng]+2); }
            #pragma unroll
            for (int ng = 0; ng < 4; ng++) { mma16816(acc[2*ng], al, bh[ng]); mma16816(acc[2*ng+1], al, bh[ng]+2); }
        }
        __syncthreads();
        if (c + 2 < 6) issue(c + 2, c & 1);
    }
    #pragma unroll
    for (int f = 0; f < 8; f++) {
        int n = n0 + (f >> 1) * 16 + (f & 1) * 8 + (lane & 3) * 2;
        #pragma unroll
        for (int rowi = 0; rowi < 2; rowi++) {
            int m = m0 + w * 16 + (lane >> 2) + rowi * 8;
            *(float2*)&g_Gx[(size_t)m * G4 + n] = make_float2(acc[f][rowi*2], acc[f][rowi*2+1]);
        }
    }
}

// ---------------- persistent LSTM kernel (bf16 3-term, pipelined fragments) ----
#define WCACHE_B 147456
#define ABUF_B   18432
#define PERSIST_SMEM (WCACHE_B + 3*ABUF_B)

__global__ void __launch_bounds__(256, 1) persist_kernel(const float* __restrict__ gx,
                                                         const float* __restrict__ benc,
                                                         const float* __restrict__ bd) {
    extern __shared__ unsigned char smem[];
    const int tid = threadIdx.x;
    const int w = tid >> 5, lane = tid & 31;
    const int wr = w & 3, wc = w >> 2;
    const int ntile = blockIdx.x, mq = blockIdx.y;
    uint32_t sbase = smem_u32(smem);
    uint32_t Wc = sbase;
    uint32_t Ab = sbase + WCACHE_B;

    const uint32_t aoff = (uint32_t)((wr * 16 + (lane & 15)) * 144 + (lane >> 4) * 16);
    const uint32_t boff = (uint32_t)((wc * 32 + ((lane >> 4) & 1) * 8 + (lane & 7)) * 144 + ((lane >> 3) & 1) * 16);

    const unsigned char* WEsrc = g_WTe + ((size_t)(ntile * 8) * 2) * WIMG;
    const unsigned char* WDsrc = g_WTd + ((size_t)(ntile * 8) * 2) * WIMG;

    auto loadW = [&](const unsigned char* src) {
        #pragma unroll 4
        for (int i = 0; i < 36; i++) {
            int idx = tid + i * 256;
            int img = idx / 576;
            int off = (idx - img * 576) * 16;
            cpasync16(Wc + img * 9216 + off, src + (size_t)img * WIMG + off);
        }
        CP_COMMIT();
    };
    auto loadA = [&](const unsigned char* Apar, int chunk, int buf) {
        #pragma unroll
        for (int i = 0; i < 5; i++) {
            int idx = tid + i * 256;
            if (idx < 1152) {
                int split = idx / 576;
                int off = (idx - split * 576) * 16;
                cpasync16(Ab + buf * ABUF_B + split * 9216 + off,
                          Apar + (size_t)(chunk * 2 + split) * AIMG + mq * 9216 + off);
            }
        }
        CP_COMMIT();
    };

    const int j0 = ntile * 16 + wc * 8 + (lane & 3) * 2;
    const int bbase = mq * 64 + wr * 16 + (lane >> 2);
    const int chunkA = ntile >> 2;
    const size_t colOff = (size_t)((ntile & 3) * 16 + wc * 8 + (lane & 3) * 2) * 2;

    float bi[4][2];
    #pragma unroll
    for (int g = 0; g < 4; g++) { bi[g][0] = benc[g * DM + j0]; bi[g][1] = benc[g * DM + j0 + 1]; }
    float creg[4] = {0.f, 0.f, 0.f, 0.f};

    loadW(WEsrc);
    CP_WAIT(0);
    __syncthreads();

    for (int s = 0; s < NSTEP; s++) {
        const bool enc = (s < TSEQ);
        if (s == TSEQ) {
            __syncthreads();
            loadW(WDsrc);
            #pragma unroll
            for (int g = 0; g < 4; g++) { bi[g][0] = bd[g * DM + j0]; bi[g][1] = bd[g * DM + j0 + 1]; }
            CP_WAIT(0);
            __syncthreads();
        }
        const int par = s & 1;
        const unsigned char* Apar = g_Hbf + (size_t)(par * 16) * AIMG;

        float pr[16];
        if (enc) {
            #pragma unroll
            for (int rowi = 0; rowi < 2; rowi++) {
                const float* gr = gx + ((size_t)(bbase + rowi * 8) * TSEQ + s) * G4;
                #pragma unroll
                for (int g = 0; g < 4; g++) {
                    float2 v = *(const float2*)&gr[g * DM + j0];
                    pr[rowi * 8 + g * 2]     = v.x;
                    pr[rowi * 8 + g * 2 + 1] = v.y;
                }
            }
        }

        float acc[4][4];
        #pragma unroll
        for (int g = 0; g < 4; g++)
            #pragma unroll
            for (int r = 0; r < 4; r++) acc[g][r] = 0.f;

        if (s > 0) {    // s==0: h=0, MMA result is all zeros — skip loads+MMA entirely
            loadA(Apar, 0, 0);
            loadA(Apar, 1, 1);
            #pragma unroll 1
            for (int c = 0; c < 8; c++) {
                if (c + 2 < 8) { loadA(Apar, c + 2, (c + 2) % 3); CP_WAIT(2); }
                else if (c == 6) { CP_WAIT(1); }
                else if (c == 7) { CP_WAIT(0); }
                __syncthreads();
                uint32_t at = Ab + (c % 3) * ABUF_B;
                uint32_t sAhi = at, sAlo = at + 9216;
                uint32_t wt = Wc + c * 18432;
                uint32_t sWhi = wt, sWlo = wt + 9216;

                // preload ALL A fragments for this chunk (latencies overlap)
                uint32_t AH[4][4], AL[4][4];
                #pragma unroll
                for (int kf = 0; kf < 4; kf++) {
                    ldsm4(AH[kf], sAhi + aoff + kf * 32);
                    ldsm4(AL[kf], sAlo + aoff + kf * 32);
                }
                // W fragments double-buffered across kf
                uint32_t WB[2][4][4];
                ldsm4(WB[0][0], sWhi + boff);
                ldsm4(WB[0][1], sWhi + boff + 2304);
                ldsm4(WB[0][2], sWlo + boff);
                ldsm4(WB[0][3], sWlo + boff + 2304);
                #pragma unroll
                for (int kf = 0; kf < 4; kf++) {
                    const int cur = kf & 1, nxt = cur ^ 1;
                    if (kf < 3) {
                        ldsm4(WB[nxt][0], sWhi + boff + (kf + 1) * 32);
                        ldsm4(WB[nxt][1], sWhi + boff + 2304 + (kf + 1) * 32);
                        ldsm4(WB[nxt][2], sWlo + boff + (kf + 1) * 32);
                        ldsm4(WB[nxt][3], sWlo + boff + 2304 + (kf + 1) * 32);
                    }
                    const uint32_t* ah = AH[kf];
                    const uint32_t* al = AL[kf];
                    mma16816(acc[0], ah, WB[cur][0]); mma16816(acc[1], ah, WB[cur][0] + 2);
                    mma16816(acc[2], ah, WB[cur][1]); mma16816(acc[3], ah, WB[cur][1] + 2);
                    mma16816(acc[0], ah, WB[cur][2]); mma16816(acc[1], ah, WB[cur][2] + 2);
                    mma16816(acc[2], ah, WB[cur][3]); mma16816(acc[3], ah, WB[cur][3] + 2);
                    mma16816(acc[0], al, WB[cur][0]); mma16816(acc[1], al, WB[cur][0] + 2);
                    mma16816(acc[2], al, WB[cur][1]); mma16816(acc[3], al, WB[cur][1] + 2);
                }
                __syncthreads();
            }
        }

        // ---- epilogue ----
        unsigned char* imgHi = g_Hbf + (size_t)(((par ^ 1) * 8 + chunkA) * 2) * AIMG;
        unsigned char* imgLo = imgHi + AIMG;
        unsigned char* decHi = nullptr;
        if (s >= TSEQ - 1) {
            int d = s - (TSEQ - 1);
            decHi = g_Dbf + (size_t)((d * 8 + chunkA) * 2) * AIMG;
        }

        #pragma unroll
        for (int rowi = 0; rowi < 2; rowi++) {
            int b = bbase + rowi * 8;
            float h2[2];
            #pragma unroll
            for (int cp = 0; cp < 2; cp++) {
                float gi = acc[0][rowi * 2 + cp] + bi[0][cp];
                float gf = acc[1][rowi * 2 + cp] + bi[1][cp];
                float gg = acc[2][rowi * 2 + cp] + bi[2][cp];
                float go = acc[3][rowi * 2 + cp] + bi[3][cp];
                if (enc) {
                    gi += pr[rowi * 8 + 0 + cp];
                    gf += pr[rowi * 8 + 2 + cp];
                    gg += pr[rowi * 8 + 4 + cp];
                    go += pr[rowi * 8 + 6 + cp];
                }
                float cn = fsig(gf) * creg[rowi * 2 + cp] + fsig(gi) * ftanh(gg);
                float hn = fsig(go) * ftanh(cn);
                creg[rowi * 2 + cp] = cn;
                h2[cp] = hn;
            }
            uint32_t hw, lw;
            bfsplit2(h2[0], h2[1], hw, lw);
            size_t off = (size_t)b * 144 + colOff;
            *(uint32_t*)(imgHi + off) = hw;
            *(uint32_t*)(imgLo + off) = lw;
            if (decHi) {
                *(uint32_t*)(decHi + off) = hw;
                *(uint32_t*)(decHi + AIMG + off) = lw;
            }
        }

        // ---- per-mq grid barrier (32 blocks, padded counter) ----
        if (s < NSTEP - 1) {
            __threadfence();
            __syncthreads();
            if (tid == 0) {
                unsigned* p = &g_bar2[(s * 4 + mq) * 32];
                unsigned prev = atomicAdd(p, 1u);
                if (prev != 31u) {
                    unsigned v;
                    do {
                        asm volatile("ld.acquire.gpu.u32 %0, [%1];" : "=r"(v) : "l"(p) : "memory");
                    } while (v < 32u);
                }
            }
            __syncthreads();
        }
    }
}

// ---------------- out: Y = Dbf @ Wp^T via HMMA, denormalize, scatter -----------
#define OSTAGE 55296
#define OUT_SMEM (2*OSTAGE)
__global__ void __launch_bounds__(256, 1) outmma_kernel(const float* __restrict__ bp,
                                                        float* __restrict__ out) {
    extern __shared__ unsigned char smem[];
    const int tid = threadIdx.x;
    const int w = tid >> 5, lane = tid & 31;
    const int ntile = blockIdx.x;        // 0..5
    const int mt = blockIdx.y;           // 0..191
    const int d = mt >> 1, half = mt & 1;
    const int m0 = half * 128;
    uint32_t sbase = smem_u32(smem);
    float acc[8][4];
    #pragma unroll
    for (int f = 0; f < 8; f++)
        #pragma unroll
        for (int r = 0; r < 4; r++) acc[f][r] = 0.f;

    const uint32_t aoff = (uint32_t)((w * 16 + (lane & 15)) * 144 + (lane >> 4) * 16);
    const uint32_t boff = (uint32_t)(((((lane >> 4) & 1) * 8) + (lane & 7)) * 144 + ((lane >> 3) & 1) * 16);
    const unsigned char* Abase = g_Dbf + (size_t)(d * 16) * AIMG;
    const unsigned char* Bbase = g_WPe + ((size_t)(ntile * 8) * 2) * WIMG;

    auto issue = [&](int chunk, int buf) {
        uint32_t sb = sbase + buf * OSTAGE;
        #pragma unroll
        for (int i = 0; i < 14; i++) {
            int idx = tid + i * 256;
            if (idx >= 3456) break;
            uint32_t dst; const unsigned char* src;
            if (idx < 2304) {
                int sp = idx / 1152; int off = (idx - sp * 1152) * 16;
                dst = sb + sp * 18432 + off;
                src = Abase + (size_t)(chunk * 2 + sp) * AIMG + (size_t)m0 * 144 + off;
            } else {
                int j = idx - 2304; int sp = j / 576; int off = (j - sp * 576) * 16;
                dst = sb + 36864 + sp * 9216 + off;
                src = Bbase + (size_t)(chunk * 2 + sp) * WIMG + off;
            }
            cpasync16(dst, src);
        }
        CP_COMMIT();
    };

    issue(0, 0); issue(1, 1);
    #pragma unroll 1
    for (int c = 0; c < 8; c++) {
        if (c < 7) { CP_WAIT(1); } else { CP_WAIT(0); }
        __syncthreads();
        uint32_t st = sbase + (c & 1) * OSTAGE;
        uint32_t sAhi = st, sAlo = st + 18432, sWhi = st + 36864, sWlo = st + 46080;
        #pragma unroll
        for (int kf = 0; kf < 4; kf++) {
            uint32_t ah[4], al[4], bh[4][4], bl[4][4];
            ldsm4(ah, sAhi + aoff + kf * 32);
            ldsm4(al, sAlo + aoff + kf * 32);
            #pragma unroll
            for (int ng = 0; ng < 4; ng++) {
                ldsm4(bh[ng], sWhi + boff + ng * 2304 + kf * 32);
                ldsm4(bl[ng], sWlo + boff + ng * 2304 + kf * 32);
            }
            #pragma unroll
            for (int ng = 0; ng < 4; ng++) { mma16816(acc[2*ng], ah, bh[ng]); mma16816(acc[2*ng+1], ah, bh[ng]+2); }
            #pragma unroll
            for (int ng = 0; ng < 4; ng++) { mma16816(acc[2*ng], ah, bl[ng]); mma16816(acc[2*ng+1], ah, bl[ng]+2); }
            #pragma unroll
            for (int ng = 0; ng < 4; ng++) { mma16816(acc[2*ng], al, bh[ng]); mma16816(acc[2*ng+1], al, bh[ng]+2); }
        }
        __syncthreads();
        if (c + 2 < 8) issue(c + 2, c & 1);
    }
    #pragma unroll
    for (int f = 0; f < 8; f++) {
        int gn = ntile * 64 + (f >> 1) * 16 + (f & 1) * 8 + (lane & 3) * 2;
        #pragma unroll
        for (int rowi = 0; rowi < 2; rowi++) {
            int b = m0 + w * 16 + (lane >> 2) + rowi * 8;
            #pragma unroll
            for (int cp = 0; cp < 2; cp++) {
                int n = gn + cp;
                if (n < CIN) {
                    int bc = b * CIN + n;
                    float y = acc[f][rowi * 2 + cp] + bp[n];
                    out[(size_t)b * PRED * CIN + (size_t)d * CIN + n] =
                        y * g_std[bc] + g_mean[bc];
                }
            }
        }
    }
}

// ---------------- host launcher ------------------------------------------------
extern "C" void kernel_launch(void* const* d_in, const int* in_sizes, int n_in,
                              void* d_out, int out_size) {
    const float* x   = (const float*)d_in[0];
    const float* Wih = (const float*)d_in[1];
    const float* Whh = (const float*)d_in[2];
    const float* bih = (const float*)d_in[3];
    const float* bhh = (const float*)d_in[4];
    const float* Wp  = (const float*)d_in[5];
    const float* bp  = (const float*)d_in[6];
    float* out = (float*)d_out;

    float *gx, *wd, *bd, *benc;
    unsigned char *wte, *wtd;
    cudaGetSymbolAddress((void**)&gx,   g_Gx);
    cudaGetSymbolAddress((void**)&wd,   g_Wd);
    cudaGetSymbolAddress((void**)&bd,   g_bd);
    cudaGetSymbolAddress((void**)&benc, g_benc);
    cudaGetSymbolAddress((void**)&wte,  g_WTe);
    cudaGetSymbolAddress((void**)&wtd,  g_WTd);

    cudaFuncSetAttribute(persist_kernel, cudaFuncAttributeMaxDynamicSharedMemorySize, PERSIST_SMEM);
    cudaFuncSetAttribute(gxmma_kernel, cudaFuncAttributeMaxDynamicSharedMemorySize, GX_SMEM);
    cudaFuncSetAttribute(outmma_kernel, cudaFuncAttributeMaxDynamicSharedMemorySize, OUT_SMEM);

    stats_kernel<<<(BATCH * CIN + 255) / 256, 256>>>(x);
    bias_kernel<<<(G4 + 255) / 256, 256>>>(bih, bhh, Wih, bp);
    wd_kernel<<<dim3(DM / 64, G4 / 64), 256>>>(Wih, Wp, Whh);
    xsplit_kernel<<<(BATCH * TSEQ * CIN + 255) / 256, 256>>>(x);
    wihsplit_kernel<<<dim3(6, 32), 256>>>(Wih);
    wpsplit_kernel<<<dim3(8, 6), 256>>>(Wp);
    wsplit_kernel<<<dim3(8, 32), 256>>>(Whh, wte);
    wsplit_kernel<<<dim3(8, 32), 256>>>(wd, wtd);
    init_kernel<<<((int)(sizeof(g_Hbf) / 4) + 255) / 256, 256>>>();
    gxmma_kernel<<<dim3(32, 192), 256, GX_SMEM>>>();

    persist_kernel<<<dim3(32, 4), 256, PERSIST_SMEM>>>(gx, benc, bd);

    outmma_kernel<<<dim3(6, 192), 256, OUT_SMEM>>>(bp, out);
    (void)in_sizes; (void)n_in; (void)out_size;
}